// round 12
// baseline (speedup 1.0000x reference)
#include <cuda_runtime.h>
#include <math.h>

#define NT 512
#define D 128
#define H 4
#define DK 32
#define M 5
#define NN 15
#define NV 64
#define PSTR 17            // padded stride for P buffers
#define PMSZ (128 * PSTR)  // 2176 floats per type

// ---------------- shared memory layout (floats) ----------------
// sm[0..4800)     : sMask (persistent)
// sm[4800..9920)  : sWW   (persistent, padded (5,64,16))
// sm[9920..10048) : sPO offset table
// S = sm + 10048, extent 47744:
//  P0/P1: Xpad S[10240..18560) stride-65 ; NIM S[0..10240)
//  P2   : PK S[10240..21120), PQ S[21120..32000), PM S[32000..42880)
//         K -> S[0..8192), Q -> S[10240..18432), MSG -> S[21120..29312)
//  P3   : A/aw -> S[29312..45696)
//  P4   : RES S[0..8192) (swizzled res2), Cpad S[8192..16512) stride-65,
//         Wmsg/ww S[16512..20608), sPart S[45696..47744); MSG + sA alive
//  P5   : NIM2 S[16512..26752), PB S[0..10880)  (Cpad read by nim)
#define SMEM_FLOATS (10048 + 47744)

typedef unsigned long long u64;

static __device__ __forceinline__ u64 bc2(float v) {
    u64 r; asm("mov.b64 %0, {%1, %1};" : "=l"(r) : "f"(v)); return r;
}
static __device__ __forceinline__ void fma2(u64& d, u64 a, u64 b) {
    asm("fma.rn.f32x2 %0, %1, %2, %0;" : "+l"(d) : "l"(a), "l"(b));
}
static __device__ __forceinline__ u64 add2(u64 a, u64 b) {
    u64 r; asm("add.rn.f32x2 %0, %1, %2;" : "=l"(r) : "l"(a), "l"(b)); return r;
}
static __device__ __forceinline__ u64 mul2(u64 a, u64 b) {
    u64 r; asm("mul.rn.f32x2 %0, %1, %2;" : "=l"(r) : "l"(a), "l"(b)); return r;
}
static __device__ __forceinline__ void unpk(u64 v, float& lo, float& hi) {
    asm("mov.b64 {%0, %1}, %2;" : "=f"(lo), "=f"(hi) : "l"(v));
}
static __device__ __forceinline__ float hsum2(u64 v) {
    float lo, hi; unpk(v, lo, hi); return lo + hi;
}
static __device__ __forceinline__ float gelu_exact(float x) {
    return 0.5f * x * (1.f + erff(x * 0.70710678118654752f));
}

// NIM[m][dd][n0..+1] = sum_nn In[dd][nn] * WW[m][nn][n0..]; 8-row x 2-col tile.
// 640 items -> full 512-thread utilization (128 threads take a second item).
static __device__ __forceinline__ void nim_calc(const float* __restrict__ sIn /*stride65*/,
                                                const float* __restrict__ sWW,
                                                float* __restrict__ sNIM, int tid) {
    for (int t = tid; t < 640; t += NT) {
        int m = t >> 7;
        int r = t & 127;
        int dd0 = (r >> 3) << 3;   // 16 row-groups of 8
        int n0 = (r & 7) << 1;     // 8 col-pairs
        const float* xb = sIn + dd0 * 65;
        const float* wb = sWW + m * 1024 + n0;
        u64 a[8];
#pragma unroll
        for (int i = 0; i < 8; i++) a[i] = 0ull;
#pragma unroll 4
        for (int nn = 0; nn < 64; nn++) {
            u64 w = *(const u64*)(wb + nn * 16);
#pragma unroll
            for (int i = 0; i < 8; i++) {
                u64 v = bc2(xb[i * 65 + nn]);
                fma2(a[i], v, w);
            }
        }
        float* o = sNIM + m * 2048 + dd0 * 16 + n0;
#pragma unroll
        for (int i = 0; i < 8; i++)
            *(u64*)(o + i * 16) = a[i];
    }
}

#define FMA4(acc, wb_)                       \
    fma2(acc[0], wb_, nv0.x); fma2(acc[1], wb_, nv0.y); \
    fma2(acc[2], wb_, nv1.x); fma2(acc[3], wb_, nv1.y);

static __device__ __forceinline__ void store8(float* __restrict__ P, int o, const u64* acc, float bias) {
#pragma unroll
    for (int p = 0; p < 4; p++) {
        float lo, hi; unpk(acc[p], lo, hi);
        P[o + 2 * p] = lo + bias;
        P[o + 2 * p + 1] = hi + bias;
    }
}

// Fused K/Q/M projection: 2-row tile (dd, dd+64), j-split 2, f32x2
static __device__ __forceinline__ void proj3(const float* __restrict__ WK, const float* __restrict__ bK,
                                             const float* __restrict__ WQ, const float* __restrict__ bQ,
                                             const float* __restrict__ WM, const float* __restrict__ bM,
                                             const float* __restrict__ sNIM,
                                             float* __restrict__ PK, float* __restrict__ PQ,
                                             float* __restrict__ PM, int tid) {
    for (int t = tid; t < 640; t += NT) {
        int pairidx = t >> 1;
        int j0 = (t & 1) << 3;
        int m = pairidx >> 6;
        int dd0 = pairidx & 63;
        const float* nb = sNIM + m * 2048 + j0;
        int ro0 = (m * 128 + dd0) * 128;
        int ro1 = ro0 + 64 * 128;
        u64 aK0[4], aK1[4], aQ0[4], aQ1[4], aM0[4], aM1[4];
#pragma unroll
        for (int j = 0; j < 4; j++) {
            aK0[j] = aK1[j] = aQ0[j] = aQ1[j] = aM0[j] = aM1[j] = 0ull;
        }
        for (int e4 = 0; e4 < 128; e4 += 4) {
            float4 wK0 = *(const float4*)(WK + ro0 + e4);
            float4 wK1 = *(const float4*)(WK + ro1 + e4);
            float4 wQ0 = *(const float4*)(WQ + ro0 + e4);
            float4 wQ1 = *(const float4*)(WQ + ro1 + e4);
            float4 wM0 = *(const float4*)(WM + ro0 + e4);
            float4 wM1 = *(const float4*)(WM + ro1 + e4);
#pragma unroll
            for (int u = 0; u < 4; u++) {
                ulonglong2 nv0 = *(const ulonglong2*)(nb + (e4 + u) * 16);
                ulonglong2 nv1 = *(const ulonglong2*)(nb + (e4 + u) * 16 + 4);
                u64 bk0 = bc2(((const float*)&wK0)[u]);
                u64 bk1 = bc2(((const float*)&wK1)[u]);
                u64 bq0 = bc2(((const float*)&wQ0)[u]);
                u64 bq1 = bc2(((const float*)&wQ1)[u]);
                u64 bm0 = bc2(((const float*)&wM0)[u]);
                u64 bm1 = bc2(((const float*)&wM1)[u]);
                FMA4(aK0, bk0) FMA4(aK1, bk1)
                FMA4(aQ0, bq0) FMA4(aQ1, bq1)
                FMA4(aM0, bm0) FMA4(aM1, bm1)
            }
        }
        int o0 = m * PMSZ + dd0 * PSTR + j0;
        int o1 = o0 + 64 * PSTR;
        store8(PK, o0, aK0, bK[m * 128 + dd0]);
        store8(PK, o1, aK1, bK[m * 128 + dd0 + 64]);
        store8(PQ, o0, aQ0, bQ[m * 128 + dd0]);
        store8(PQ, o1, aQ1, bQ[m * 128 + dd0 + 64]);
        store8(PM, o0, aM0, bM[m * 128 + dd0]);
        store8(PM, o1, aM1, bM[m * 128 + dd0 + 64]);
    }
}

// single projection (WB): 4-row tile, j-split 2, f32x2, 2-stage weight pipeline
static __device__ __forceinline__ void proj1(const float* __restrict__ W, const float* __restrict__ bg,
                                             const float* __restrict__ sNIM, float* __restrict__ P,
                                             int tid) {
    for (int t = tid; t < 320; t += NT) {
        int gidx = t >> 1;
        int j0 = (t & 1) << 3;
        int m = gidx >> 5;
        int dd0 = gidx & 31;
        const float* nb = sNIM + m * 2048 + j0;
        int ro[4];
#pragma unroll
        for (int i = 0; i < 4; i++) ro[i] = (m * 128 + dd0 + 32 * i) * 128;
        u64 a0[4], a1[4], a2[4], a3[4];
#pragma unroll
        for (int j = 0; j < 4; j++) { a0[j] = a1[j] = a2[j] = a3[j] = 0ull; }
        // prefetch first weight quad
        float4 w0 = *(const float4*)(W + ro[0]);
        float4 w1 = *(const float4*)(W + ro[1]);
        float4 w2 = *(const float4*)(W + ro[2]);
        float4 w3 = *(const float4*)(W + ro[3]);
        for (int e4 = 0; e4 < 128; e4 += 4) {
            float4 t0, t1, t2, t3;
            if (e4 < 124) {
                t0 = *(const float4*)(W + ro[0] + e4 + 4);
                t1 = *(const float4*)(W + ro[1] + e4 + 4);
                t2 = *(const float4*)(W + ro[2] + e4 + 4);
                t3 = *(const float4*)(W + ro[3] + e4 + 4);
            }
#pragma unroll
            for (int u = 0; u < 4; u++) {
                ulonglong2 nv0 = *(const ulonglong2*)(nb + (e4 + u) * 16);
                ulonglong2 nv1 = *(const ulonglong2*)(nb + (e4 + u) * 16 + 4);
                u64 b0 = bc2(((const float*)&w0)[u]);
                u64 b1 = bc2(((const float*)&w1)[u]);
                u64 b2 = bc2(((const float*)&w2)[u]);
                u64 b3 = bc2(((const float*)&w3)[u]);
                FMA4(a0, b0) FMA4(a1, b1) FMA4(a2, b2) FMA4(a3, b3)
            }
            if (e4 < 124) { w0 = t0; w1 = t1; w2 = t2; w3 = t3; }
        }
#pragma unroll
        for (int i = 0; i < 4; i++) {
            const u64* acc = (i == 0) ? a0 : (i == 1) ? a1 : (i == 2) ? a2 : a3;
            int o = m * PMSZ + (dd0 + 32 * i) * PSTR + j0;
            store8(P, o, acc, bg[m * 128 + dd0 + 32 * i]);
        }
    }
}

// stage1: ww[ii][j] = aw[h][i0+ii][j%64] * AM[i0+ii][j], XOR-swizzled; 1024 items
static __device__ __forceinline__ void stage1_ww(const float* __restrict__ sA,
                                                 const float* __restrict__ AMg,
                                                 float* __restrict__ sWB4,
                                                 int h, int i0, int tid) {
#pragma unroll
    for (int rep = 0; rep < 2; rep++) {
        int idx = tid + rep * NT;
        int ii = idx >> 6;
        int j4 = (idx & 63) << 2;
        int i = i0 + ii;
        float4 am = *(const float4*)(AMg + i * 256 + j4);
        float4 av = *(const float4*)(sA + (h * 64 + i) * 64 + (j4 & 63));
        float4 w;
        w.x = av.x * am.x; w.y = av.y * am.y; w.z = av.z * am.z; w.w = av.w * am.w;
        *(float4*)(sWB4 + ii * 256 + (j4 ^ (ii << 2))) = w;
    }
}

// Wmsg load (head-independent), swizzled [q][(kk+q)&31]
static __device__ __forceinline__ void load_wmsg(float* __restrict__ sWB4,
                                                 const float* __restrict__ Wup,
                                                 const float* __restrict__ Wdn,
                                                 const float* __restrict__ Wlf,
                                                 const float* __restrict__ Wrt, int tid) {
#pragma unroll
    for (int rep = 0; rep < 8; rep++) {
        int i = tid + rep * NT;
        int q = i >> 5, kk = i & 31;
        int dir = q >> 5, col = q & 31;
        const float* Wd = (dir == 0) ? Wup : (dir == 1) ? Wdn : (dir == 2) ? Wlf : Wrt;
        sWB4[(q << 5) + ((kk + q) & 31)] = Wd[kk * 32 + col];
    }
}

__global__ void __launch_bounds__(NT, 1)
hgt_kernel(const float* __restrict__ node, const float* __restrict__ WWg,
           const float* __restrict__ maskg, const float* __restrict__ Rg,
           const float* __restrict__ AMg,
           const float* __restrict__ WKg, const float* __restrict__ bKg,
           const float* __restrict__ WQg, const float* __restrict__ bQg,
           const float* __restrict__ WMg, const float* __restrict__ bMg,
           const float* __restrict__ WBg, const float* __restrict__ bBg,
           const float* __restrict__ Wup, const float* __restrict__ Wdn,
           const float* __restrict__ Wlf, const float* __restrict__ Wrt,
           float* __restrict__ outp, int nb) {
    const int b = blockIdx.x;
    const int tid = threadIdx.x;
    const int BS = nb * NV;
    extern __shared__ float sm[];
    float* sMask = sm;
    float* sWW = sm + 4800;
    int* sPO = (int*)(sm + 9920);
    float* S = sm + 10048;

    // ---- P0: loads ----
    for (int i = tid; i < 4800; i += NT) sMask[i] = maskg[i];
    for (int i = tid; i < 4800; i += NT) {
        int m = i / 960;
        int r = i - m * 960;
        int nn = r / 15;
        int N = r - nn * 15;
        sWW[m * 1024 + nn * 16 + N] = WWg[b * 4800 + i];
    }
    for (int i = tid; i < 320; i += NT) sWW[i * 16 + 15] = 0.f;
    if (tid < 75) sPO[tid] = (tid / 15) * PMSZ + (tid % 15);
    {
        float* sX = S + 10240;
        for (int i = tid; i < 8192; i += NT) {
            int d = i >> 6, nn = i & 63;
            sX[d * 65 + nn] = node[d * BS + b * 64 + nn];
        }
    }
    __syncthreads();

    // ---- P1: NIM ----
    float* sNIM = S;
    nim_calc(S + 10240, sWW, sNIM, tid);
    __syncthreads();

    // ---- P2: fused K/Q/M projection + FUSED 3-way mask matmul ----
    float* sPK = S + 10240;
    float* sPQ = S + 21120;
    float* sPM = S + 32000;
    float* sK = S;
    float* sQ = S + 10240;
    float* sMSG = S + 21120;

    proj3(WKg, bKg, WQg, bQg, WMg, bMg, sNIM, sPK, sPQ, sPM, tid);
    __syncthreads();
    // fused K+Q+M maskmul: one bm read feeds all three; Q and M stores deferred
    {
        int t = tid;
        int dg = t >> 4, n0 = (t & 15) << 2;
        u64 k0[2], k1[2], k2[2], k3[2];
        u64 q0[2], q1[2], q2[2], q3[2];
        u64 g0[2], g1[2], g2[2], g3[2];
        k0[0] = k0[1] = k1[0] = k1[1] = k2[0] = k2[1] = k3[0] = k3[1] = 0ull;
        q0[0] = q0[1] = q1[0] = q1[1] = q2[0] = q2[1] = q3[0] = q3[1] = 0ull;
        g0[0] = g0[1] = g1[0] = g1[1] = g2[0] = g2[1] = g3[0] = g3[1] = 0ull;
        int r0 = dg * PSTR, r1 = (dg + 32) * PSTR, r2 = (dg + 64) * PSTR, r3 = (dg + 96) * PSTR;
        int mC[4], ddC[4], NC[4];
#pragma unroll
        for (int i = 0; i < 4; i++) {
            int f = (dg + 32 * i) * 75;
            mC[i] = f / 1920;
            int r = f - mC[i] * 1920;
            ddC[i] = r / 15;
            NC[i] = r - ddC[i] * 15;
        }
        for (int j = 0; j < 75; j++) {
            int po = sPO[j];
            ulonglong2 bm = *(const ulonglong2*)(sMask + j * 64 + n0);
            u64 sk0 = bc2(sPK[r0 + po]);
            u64 sk1 = bc2(sPK[r1 + po]);
            u64 sk2 = bc2(sPK[r2 + po]);
            u64 sk3 = bc2(sPK[r3 + po]);
            fma2(k0[0], sk0, bm.x); fma2(k0[1], sk0, bm.y);
            fma2(k1[0], sk1, bm.x); fma2(k1[1], sk1, bm.y);
            fma2(k2[0], sk2, bm.x); fma2(k2[1], sk2, bm.y);
            fma2(k3[0], sk3, bm.x); fma2(k3[1], sk3, bm.y);
            u64 sq0 = bc2(sPQ[r0 + po]);
            u64 sq1 = bc2(sPQ[r1 + po]);
            u64 sq2 = bc2(sPQ[r2 + po]);
            u64 sq3 = bc2(sPQ[r3 + po]);
            fma2(q0[0], sq0, bm.x); fma2(q0[1], sq0, bm.y);
            fma2(q1[0], sq1, bm.x); fma2(q1[1], sq1, bm.y);
            fma2(q2[0], sq2, bm.x); fma2(q2[1], sq2, bm.y);
            fma2(q3[0], sq3, bm.x); fma2(q3[1], sq3, bm.y);
            u64 sm0 = bc2(sPM[mC[0] * PMSZ + ddC[0] * PSTR + NC[0]]);
            u64 sm1 = bc2(sPM[mC[1] * PMSZ + ddC[1] * PSTR + NC[1]]);
            u64 sm2 = bc2(sPM[mC[2] * PMSZ + ddC[2] * PSTR + NC[2]]);
            u64 sm3 = bc2(sPM[mC[3] * PMSZ + ddC[3] * PSTR + NC[3]]);
            fma2(g0[0], sm0, bm.x); fma2(g0[1], sm0, bm.y);
            fma2(g1[0], sm1, bm.x); fma2(g1[1], sm1, bm.y);
            fma2(g2[0], sm2, bm.x); fma2(g2[1], sm2, bm.y);
            fma2(g3[0], sm3, bm.x); fma2(g3[1], sm3, bm.y);
#pragma unroll
            for (int i = 0; i < 4; i++) {
                if (++NC[i] == 15) {
                    NC[i] = 0;
                    if (++ddC[i] == 128) { ddC[i] = 0; ++mC[i]; }
                }
            }
        }
        *(ulonglong2*)(sK + dg * 64 + n0) = make_ulonglong2(k0[0], k0[1]);
        *(ulonglong2*)(sK + (dg + 32) * 64 + n0) = make_ulonglong2(k1[0], k1[1]);
        *(ulonglong2*)(sK + (dg + 64) * 64 + n0) = make_ulonglong2(k2[0], k2[1]);
        *(ulonglong2*)(sK + (dg + 96) * 64 + n0) = make_ulonglong2(k3[0], k3[1]);
        __syncthreads();  // all PK/PQ/PM reads done; regions reusable
        *(ulonglong2*)(sQ + dg * 64 + n0) = make_ulonglong2(q0[0], q0[1]);
        *(ulonglong2*)(sQ + (dg + 32) * 64 + n0) = make_ulonglong2(q1[0], q1[1]);
        *(ulonglong2*)(sQ + (dg + 64) * 64 + n0) = make_ulonglong2(q2[0], q2[1]);
        *(ulonglong2*)(sQ + (dg + 96) * 64 + n0) = make_ulonglong2(q3[0], q3[1]);
        *(ulonglong2*)(sMSG + dg * 64 + n0) = make_ulonglong2(g0[0], g0[1]);
        *(ulonglong2*)(sMSG + (dg + 32) * 64 + n0) = make_ulonglong2(g1[0], g1[1]);
        *(ulonglong2*)(sMSG + (dg + 64) * 64 + n0) = make_ulonglong2(g2[0], g2[1]);
        *(ulonglong2*)(sMSG + (dg + 96) * 64 + n0) = make_ulonglong2(g3[0], g3[1]);
    }
    __syncthreads();

    // ---- P3: A = Q^T K / sqrt(dk) (4-row tile), softmax(R+A) ----
    float* sA = S + 29312;
    {
        int t = tid;
        int h = t >> 7, rem = t & 127, i0r = rem >> 3, j0 = (rem & 7) << 3;
        u64 a[4][4];
#pragma unroll
        for (int c = 0; c < 4; c++)
#pragma unroll
            for (int j = 0; j < 4; j++) a[c][j] = 0ull;
        for (int k = 0; k < 32; k++) {
            const float* kr = sK + (h * 32 + k) * 64 + j0;
            const float* qr = sQ + (h * 32 + k) * 64;
            ulonglong2 nv0 = *(const ulonglong2*)(kr);
            ulonglong2 nv1 = *(const ulonglong2*)(kr + 4);
#pragma unroll
            for (int c = 0; c < 4; c++) {
                u64 qv = bc2(qr[i0r + 16 * c]);
                FMA4(a[c], qv)
            }
        }
        u64 s2 = bc2(0.17677669529663687f);
#pragma unroll
        for (int c = 0; c < 4; c++) {
#pragma unroll
            for (int j = 0; j < 4; j++) a[c][j] = mul2(a[c][j], s2);
            float* o = sA + (h * 64 + i0r + 16 * c) * 64 + j0;
            *(ulonglong2*)(o) = make_ulonglong2(a[c][0], a[c][1]);
            *(ulonglong2*)(o + 4) = make_ulonglong2(a[c][2], a[c][3]);
        }
    }
    __syncthreads();

    {
        int warp = tid >> 5, lane = tid & 31;
        for (int r = warp; r < 256; r += NT / 32) {
            float* row = sA + r * 64;
            const float* rrow = Rg + b * 16384 + r * 64;
            float v0 = row[lane] + rrow[lane];
            float v1 = row[lane + 32] + rrow[lane + 32];
            float mx = fmaxf(v0, v1);
#pragma unroll
            for (int o = 16; o > 0; o >>= 1) mx = fmaxf(mx, __shfl_xor_sync(0xffffffffu, mx, o));
            float e0 = __expf(v0 - mx), e1 = __expf(v1 - mx);
            float sum = e0 + e1;
#pragma unroll
            for (int o = 16; o > 0; o >>= 1) sum += __shfl_xor_sync(0xffffffffu, sum, o);
            float inv = 1.f / sum;
            row[lane] = e0 * inv;
            row[lane + 32] = e1 * inv;
        }
    }
    __syncthreads();

    // ---- P4 buffers ----
    float* sRES = S;            // swizzled res2 [32][256]
    float* sCpad = S + 8192;    // stride-65 gelu output
    float* sWB4 = S + 16512;    // Wmsg / ww tile
    float* sPart = S + 45696;   // 2048 split-K partials

    // aw[0,0] output (b==0) fused with head-0 Wmsg load
    if (b == 0) {
        for (int idx = tid; idx < 4096; idx += NT) {
            int ii = idx >> 6, j4 = (idx & 63) << 2;
            float4 am = *(const float4*)(AMg + ii * 256 + j4);
            float4 av = *(const float4*)(sA + ii * 64 + (j4 & 63));
            float4 o;
            o.x = av.x * am.x; o.y = av.y * am.y; o.z = av.z * am.z; o.w = av.w * am.w;
            *(float4*)(outp + D * BS + ii * 256 + j4) = o;
        }
    }
    load_wmsg(sWB4, Wup, Wdn, Wlf, Wrt, tid);
    __syncthreads();

    // ---- P4: per-head res + masked attention apply + gelu -> Cpad ----
    for (int h = 0; h < 4; h++) {
        // RES (512 threads, 4q x 4n) -> swizzled res2
        {
            int qg = tid >> 4;
            int n0 = (tid & 15) << 2;
            u64 c[4][2];
#pragma unroll
            for (int s = 0; s < 4; s++) { c[s][0] = 0ull; c[s][1] = 0ull; }
            for (int kk = 0; kk < 32; kk++) {
                const float* mr = sMSG + (h * 32 + kk) * 64 + n0;
                ulonglong2 nv = *(const ulonglong2*)(mr);
#pragma unroll
                for (int s = 0; s < 4; s++) {
                    int q = qg + 32 * s;
                    u64 w = bc2(sWB4[(q << 5) + ((kk + q) & 31)]);
                    fma2(c[s][0], w, nv.x);
                    fma2(c[s][1], w, nv.y);
                }
            }
#pragma unroll
            for (int s = 0; s < 4; s++) {
                int q = qg + 32 * s;
                int kq = q >> 2;
                int off = ((q & 3) << 6) + n0;
                int sw = (kq & 7) << 2;
                *(ulonglong2*)(sRES + (kq << 8) + (off ^ sw)) =
                    make_ulonglong2(c[s][0], c[s][1]);
            }
        }
        __syncthreads();  // RES done; sWB4 (Wmsg) free to become ww
        stage1_ww(sA, AMg, sWB4, h, 0, tid);
        __syncthreads();

        for (int i0 = 0; i0 < 64; i0 += 16) {
            // stage2: 4-way split-K x 2 ii-halves across 8 warps, 4k x 2ii tiles
            if (tid < 256) {
                int warp = tid >> 5;
                int g = warp & 3;        // j2 quarter
                int half = warp >> 2;    // ii half
                int r = tid & 31;
                int kp = r >> 2;         // 0..7
                int iip = r & 3;         // 0..3
                int jbase = g << 6;
                int ksw = kp << 2;
                int iiA = half * 8 + iip;
                int iiB = iiA + 4;
                const float* wA = sWB4 + (iiA << 8);
                const float* wB = sWB4 + (iiB << 8);
                int swA = iiA << 2, swB = iiB << 2;
                u64 acc[4][2];
#pragma unroll
                for (int c = 0; c < 4; c++) { acc[c][0] = 0ull; acc[c][1] = 0ull; }
#pragma unroll 4
                for (int jj = 0; jj < 64; jj += 4) {
                    int j2 = jbase + jj;
                    int jx = j2 ^ ksw;
                    ulonglong2 rv[4];
#pragma unroll
                    for (int c = 0; c < 4; c++)
                        rv[c] = *(const ulonglong2*)(sRES + ((kp + 8 * c) << 8) + jx);
                    ulonglong2 wvA = *(const ulonglong2*)(wA + (j2 ^ swA));
                    ulonglong2 wvB = *(const ulonglong2*)(wB + (j2 ^ swB));
#pragma unroll
                    for (int c = 0; c < 4; c++) {
                        fma2(acc[c][0], rv[c].x, wvA.x);
                        fma2(acc[c][0], rv[c].y, wvA.y);
                        fma2(acc[c][1], rv[c].x, wvB.x);
                        fma2(acc[c][1], rv[c].y, wvB.y);
                    }
                }
                int gb = g << 9;
#pragma unroll
                for (int c = 0; c < 4; c++) {
                    int k = kp + 8 * c;
                    sPart[gb + (k << 4) + iiA] = hsum2(acc[c][0]);
                    sPart[gb + (k << 4) + iiB] = hsum2(acc[c][1]);
                }
            }
            __syncthreads();
            // stage3: reduce + gelu -> Cpad ; fused with stage1(next) or Wmsg(next head)
            {
                float v = sPart[tid] + sPart[512 + tid] + sPart[1024 + tid] + sPart[1536 + tid];
                int k = tid >> 4, ii = tid & 15;
                sCpad[(h * 32 + k) * 65 + i0 + ii] = gelu_exact(v);
            }
            if (i0 < 48) {
                stage1_ww(sA, AMg, sWB4, h, i0 + 16, tid);
            } else if (h < 3) {
                load_wmsg(sWB4, Wup, Wdn, Wlf, Wrt, tid);
            }
            __syncthreads();
        }
    }

    // ---- P5: back-projection + residual (Cpad already stride-65) ----
    float* sNIM2 = S + 16512;
    nim_calc(sCpad, sWW, sNIM2, tid);
    __syncthreads();
    float* sPB = S;
    proj1(WBg, bBg, sNIM2, sPB, tid);
    __syncthreads();

    for (int t = tid; t < 512; t += NT) {
        int dg = t >> 4, n0 = (t & 15) << 2;
        u64 a0[2], a1[2], a2[2], a3[2];
        a0[0] = a0[1] = a1[0] = a1[1] = a2[0] = a2[1] = a3[0] = a3[1] = 0ull;
        const float* p0 = sPB + dg * PSTR;
        const float* p1 = sPB + (dg + 32) * PSTR;
        const float* p2 = sPB + (dg + 64) * PSTR;
        const float* p3 = sPB + (dg + 96) * PSTR;
        for (int j = 0; j < 75; j++) {
            int po = sPO[j];
            u64 s0 = bc2(p0[po]);
            u64 s1 = bc2(p1[po]);
            u64 s2 = bc2(p2[po]);
            u64 s3 = bc2(p3[po]);
            ulonglong2 bm = *(const ulonglong2*)(sMask + j * 64 + n0);
            fma2(a0[0], s0, bm.x); fma2(a0[1], s0, bm.y);
            fma2(a1[0], s1, bm.x); fma2(a1[1], s1, bm.y);
            fma2(a2[0], s2, bm.x); fma2(a2[1], s2, bm.y);
            fma2(a3[0], s3, bm.x); fma2(a3[1], s3, bm.y);
        }
#pragma unroll
        for (int i = 0; i < 4; i++) {
            const u64* acc = (i == 0) ? a0 : (i == 1) ? a1 : (i == 2) ? a2 : a3;
            int d = dg + 32 * i;
            int gi = d * BS + b * 64 + n0;
            ulonglong2 rr = *(const ulonglong2*)(node + gi);
            *(ulonglong2*)(outp + gi) =
                make_ulonglong2(add2(acc[0], rr.x), add2(acc[1], rr.y));
        }
    }
}

extern "C" void kernel_launch(void* const* d_in, const int* in_sizes, int n_in,
                              void* d_out, int out_size) {
    const float* node = (const float*)d_in[0];
    const float* WWg = (const float*)d_in[1];
    const float* maskg = (const float*)d_in[2];
    const float* Rg = (const float*)d_in[3];
    const float* AMg = (const float*)d_in[4];
    const float* WKg = (const float*)d_in[5];
    const float* bKg = (const float*)d_in[6];
    const float* WQg = (const float*)d_in[7];
    const float* bQg = (const float*)d_in[8];
    const float* WMg = (const float*)d_in[9];
    const float* bMg = (const float*)d_in[10];
    const float* WBg = (const float*)d_in[11];
    const float* bBg = (const float*)d_in[12];
    const float* Wup = (const float*)d_in[13];
    const float* Wdn = (const float*)d_in[14];
    const float* Wlf = (const float*)d_in[15];
    const float* Wrt = (const float*)d_in[16];
    float* outp = (float*)d_out;

    int nb = in_sizes[0] / (D * NV);
    size_t smem = SMEM_FLOATS * sizeof(float);
    cudaFuncSetAttribute(hgt_kernel, cudaFuncAttributeMaxDynamicSharedMemorySize, (int)smem);
    hgt_kernel<<<nb, NT, smem>>>(node, WWg, maskg, Rg, AMg, WKg, bKg, WQg, bQg,
                                 WMg, bMg, WBg, bBg, Wup, Wdn, Wlf, Wrt, outp, nb);
}

// round 13
// speedup vs baseline: 1.0227x; 1.0227x over previous
#include <cuda_runtime.h>
#include <math.h>

#define NT 512
#define D 128
#define H 4
#define DK 32
#define M 5
#define NN 15
#define NV 64
#define PSTR 17            // padded stride for P buffers
#define PMSZ (128 * PSTR)  // 2176 floats per type

// ---------------- shared memory layout (floats) ----------------
// sm[0..4800)     : sMask (persistent)
// sm[4800..9920)  : sWW   (persistent, padded (5,64,16))
// sm[9920..10048) : sPO offset table
// S = sm + 10048, extent 47744:
//  P0/P1: Xpad S[10240..18560) stride-65 ; NIM S[0..10240)
//  P2   : PK S[10240..21120), PQ S[21120..32000), PM S[32000..42880)
//         K -> S[0..8192), Q -> S[10240..18432), MSG -> S[21120..29312)
//  P3   : A/aw -> S[29312..45696)
//  P4   : RES S[0..8192) (swizzled res2), Cpad S[8192..16512) stride-65,
//         Wmsg/ww S[16512..20608), sPart S[45696..47744); MSG + sA alive
//  P5   : NIM2 S[16512..26752), PB S[0..10880)  (Cpad read by nim)
#define SMEM_FLOATS (10048 + 47744)

typedef unsigned long long u64;

static __device__ __forceinline__ u64 bc2(float v) {
    u64 r; asm("mov.b64 %0, {%1, %1};" : "=l"(r) : "f"(v)); return r;
}
static __device__ __forceinline__ void fma2(u64& d, u64 a, u64 b) {
    asm("fma.rn.f32x2 %0, %1, %2, %0;" : "+l"(d) : "l"(a), "l"(b));
}
static __device__ __forceinline__ u64 add2(u64 a, u64 b) {
    u64 r; asm("add.rn.f32x2 %0, %1, %2;" : "=l"(r) : "l"(a), "l"(b)); return r;
}
static __device__ __forceinline__ u64 mul2(u64 a, u64 b) {
    u64 r; asm("mul.rn.f32x2 %0, %1, %2;" : "=l"(r) : "l"(a), "l"(b)); return r;
}
static __device__ __forceinline__ void unpk(u64 v, float& lo, float& hi) {
    asm("mov.b64 {%0, %1}, %2;" : "=f"(lo), "=f"(hi) : "l"(v));
}
static __device__ __forceinline__ float hsum2(u64 v) {
    float lo, hi; unpk(v, lo, hi); return lo + hi;
}
static __device__ __forceinline__ float gelu_exact(float x) {
    return 0.5f * x * (1.f + erff(x * 0.70710678118654752f));
}

// NIM[m][dd][n0..+3] = sum_nn In[dd][nn] * WW[m][nn][n0..]; 8-row x 4-col tile
static __device__ __forceinline__ void nim_calc8(const float* __restrict__ sIn /*stride65*/,
                                                 const float* __restrict__ sWW,
                                                 float* __restrict__ sNIM, int tid) {
    for (int t = tid; t < 320; t += NT) {
        int m = t >> 6;
        int r = t & 63;
        int dd0 = (r >> 2) << 3;
        int n0 = (r & 3) << 2;
        const float* xb = sIn + dd0 * 65;
        const float* wb = sWW + m * 1024 + n0;
        u64 a[8][2];
#pragma unroll
        for (int i = 0; i < 8; i++) { a[i][0] = 0ull; a[i][1] = 0ull; }
#pragma unroll 4
        for (int nn = 0; nn < 64; nn++) {
            ulonglong2 w = *(const ulonglong2*)(wb + nn * 16);
#pragma unroll
            for (int i = 0; i < 8; i++) {
                u64 v = bc2(xb[i * 65 + nn]);
                fma2(a[i][0], v, w.x);
                fma2(a[i][1], v, w.y);
            }
        }
        float* o = sNIM + m * 2048 + dd0 * 16 + n0;
#pragma unroll
        for (int i = 0; i < 8; i++)
            *(ulonglong2*)(o + i * 16) = make_ulonglong2(a[i][0], a[i][1]);
    }
}

#define FMA4(acc, wb_)                       \
    fma2(acc[0], wb_, nv0.x); fma2(acc[1], wb_, nv0.y); \
    fma2(acc[2], wb_, nv1.x); fma2(acc[3], wb_, nv1.y);

static __device__ __forceinline__ void store8(float* __restrict__ P, int o, const u64* acc, float bias) {
#pragma unroll
    for (int p = 0; p < 4; p++) {
        float lo, hi; unpk(acc[p], lo, hi);
        P[o + 2 * p] = lo + bias;
        P[o + 2 * p + 1] = hi + bias;
    }
}

// Fused K/Q/M projection: 2-row tile (dd, dd+64), j-split 2, f32x2
static __device__ __forceinline__ void proj3(const float* __restrict__ WK, const float* __restrict__ bK,
                                             const float* __restrict__ WQ, const float* __restrict__ bQ,
                                             const float* __restrict__ WM, const float* __restrict__ bM,
                                             const float* __restrict__ sNIM,
                                             float* __restrict__ PK, float* __restrict__ PQ,
                                             float* __restrict__ PM, int tid) {
    for (int t = tid; t < 640; t += NT) {
        int pairidx = t >> 1;
        int j0 = (t & 1) << 3;
        int m = pairidx >> 6;
        int dd0 = pairidx & 63;
        const float* nb = sNIM + m * 2048 + j0;
        int ro0 = (m * 128 + dd0) * 128;
        int ro1 = ro0 + 64 * 128;
        u64 aK0[4], aK1[4], aQ0[4], aQ1[4], aM0[4], aM1[4];
#pragma unroll
        for (int j = 0; j < 4; j++) {
            aK0[j] = aK1[j] = aQ0[j] = aQ1[j] = aM0[j] = aM1[j] = 0ull;
        }
        for (int e4 = 0; e4 < 128; e4 += 4) {
            float4 wK0 = *(const float4*)(WK + ro0 + e4);
            float4 wK1 = *(const float4*)(WK + ro1 + e4);
            float4 wQ0 = *(const float4*)(WQ + ro0 + e4);
            float4 wQ1 = *(const float4*)(WQ + ro1 + e4);
            float4 wM0 = *(const float4*)(WM + ro0 + e4);
            float4 wM1 = *(const float4*)(WM + ro1 + e4);
#pragma unroll
            for (int u = 0; u < 4; u++) {
                ulonglong2 nv0 = *(const ulonglong2*)(nb + (e4 + u) * 16);
                ulonglong2 nv1 = *(const ulonglong2*)(nb + (e4 + u) * 16 + 4);
                u64 bk0 = bc2(((const float*)&wK0)[u]);
                u64 bk1 = bc2(((const float*)&wK1)[u]);
                u64 bq0 = bc2(((const float*)&wQ0)[u]);
                u64 bq1 = bc2(((const float*)&wQ1)[u]);
                u64 bm0 = bc2(((const float*)&wM0)[u]);
                u64 bm1 = bc2(((const float*)&wM1)[u]);
                FMA4(aK0, bk0) FMA4(aK1, bk1)
                FMA4(aQ0, bq0) FMA4(aQ1, bq1)
                FMA4(aM0, bm0) FMA4(aM1, bm1)
            }
        }
        int o0 = m * PMSZ + dd0 * PSTR + j0;
        int o1 = o0 + 64 * PSTR;
        store8(PK, o0, aK0, bK[m * 128 + dd0]);
        store8(PK, o1, aK1, bK[m * 128 + dd0 + 64]);
        store8(PQ, o0, aQ0, bQ[m * 128 + dd0]);
        store8(PQ, o1, aQ1, bQ[m * 128 + dd0 + 64]);
        store8(PM, o0, aM0, bM[m * 128 + dd0]);
        store8(PM, o1, aM1, bM[m * 128 + dd0 + 64]);
    }
}

// single projection (WB): 4-row tile, j-split 2, f32x2
static __device__ __forceinline__ void proj1(const float* __restrict__ W, const float* __restrict__ bg,
                                             const float* __restrict__ sNIM, float* __restrict__ P,
                                             int tid) {
    for (int t = tid; t < 320; t += NT) {
        int gidx = t >> 1;
        int j0 = (t & 1) << 3;
        int m = gidx >> 5;
        int dd0 = gidx & 31;
        const float* nb = sNIM + m * 2048 + j0;
        int ro[4];
#pragma unroll
        for (int i = 0; i < 4; i++) ro[i] = (m * 128 + dd0 + 32 * i) * 128;
        u64 a0[4], a1[4], a2[4], a3[4];
#pragma unroll
        for (int j = 0; j < 4; j++) { a0[j] = a1[j] = a2[j] = a3[j] = 0ull; }
        for (int e4 = 0; e4 < 128; e4 += 4) {
            float4 w0 = *(const float4*)(W + ro[0] + e4);
            float4 w1 = *(const float4*)(W + ro[1] + e4);
            float4 w2 = *(const float4*)(W + ro[2] + e4);
            float4 w3 = *(const float4*)(W + ro[3] + e4);
#pragma unroll
            for (int u = 0; u < 4; u++) {
                ulonglong2 nv0 = *(const ulonglong2*)(nb + (e4 + u) * 16);
                ulonglong2 nv1 = *(const ulonglong2*)(nb + (e4 + u) * 16 + 4);
                u64 b0 = bc2(((const float*)&w0)[u]);
                u64 b1 = bc2(((const float*)&w1)[u]);
                u64 b2 = bc2(((const float*)&w2)[u]);
                u64 b3 = bc2(((const float*)&w3)[u]);
                FMA4(a0, b0) FMA4(a1, b1) FMA4(a2, b2) FMA4(a3, b3)
            }
        }
#pragma unroll
        for (int i = 0; i < 4; i++) {
            const u64* acc = (i == 0) ? a0 : (i == 1) ? a1 : (i == 2) ? a2 : a3;
            int o = m * PMSZ + (dd0 + 32 * i) * PSTR + j0;
            store8(P, o, acc, bg[m * 128 + dd0 + 32 * i]);
        }
    }
}

// stage1: ww[ii][j] = aw[h][i0+ii][j%64] * AM[i0+ii][j], XOR-swizzled; 1024 items
static __device__ __forceinline__ void stage1_ww(const float* __restrict__ sA,
                                                 const float* __restrict__ AMg,
                                                 float* __restrict__ sWB4,
                                                 int h, int i0, int tid) {
#pragma unroll
    for (int rep = 0; rep < 2; rep++) {
        int idx = tid + rep * NT;
        int ii = idx >> 6;
        int j4 = (idx & 63) << 2;
        int i = i0 + ii;
        float4 am = *(const float4*)(AMg + i * 256 + j4);
        float4 av = *(const float4*)(sA + (h * 64 + i) * 64 + (j4 & 63));
        float4 w;
        w.x = av.x * am.x; w.y = av.y * am.y; w.z = av.z * am.z; w.w = av.w * am.w;
        *(float4*)(sWB4 + ii * 256 + (j4 ^ (ii << 2))) = w;
    }
}

// Wmsg load (head-independent), swizzled [q][(kk+q)&31]
static __device__ __forceinline__ void load_wmsg(float* __restrict__ sWB4,
                                                 const float* __restrict__ Wup,
                                                 const float* __restrict__ Wdn,
                                                 const float* __restrict__ Wlf,
                                                 const float* __restrict__ Wrt, int tid) {
#pragma unroll
    for (int rep = 0; rep < 8; rep++) {
        int i = tid + rep * NT;
        int q = i >> 5, kk = i & 31;
        int dir = q >> 5, col = q & 31;
        const float* Wd = (dir == 0) ? Wup : (dir == 1) ? Wdn : (dir == 2) ? Wlf : Wrt;
        sWB4[(q << 5) + ((kk + q) & 31)] = Wd[kk * 32 + col];
    }
}

__global__ void __launch_bounds__(NT, 1)
hgt_kernel(const float* __restrict__ node, const float* __restrict__ WWg,
           const float* __restrict__ maskg, const float* __restrict__ Rg,
           const float* __restrict__ AMg,
           const float* __restrict__ WKg, const float* __restrict__ bKg,
           const float* __restrict__ WQg, const float* __restrict__ bQg,
           const float* __restrict__ WMg, const float* __restrict__ bMg,
           const float* __restrict__ WBg, const float* __restrict__ bBg,
           const float* __restrict__ Wup, const float* __restrict__ Wdn,
           const float* __restrict__ Wlf, const float* __restrict__ Wrt,
           float* __restrict__ outp, int nb) {
    const int b = blockIdx.x;
    const int tid = threadIdx.x;
    const int BS = nb * NV;
    extern __shared__ float sm[];
    float* sMask = sm;
    float* sWW = sm + 4800;
    int* sPO = (int*)(sm + 9920);
    float* S = sm + 10048;

    // ---- P0: loads ----
    for (int i = tid; i < 4800; i += NT) sMask[i] = maskg[i];
    for (int i = tid; i < 4800; i += NT) {
        int m = i / 960;
        int r = i - m * 960;
        int nn = r / 15;
        int N = r - nn * 15;
        sWW[m * 1024 + nn * 16 + N] = WWg[b * 4800 + i];
    }
    for (int i = tid; i < 320; i += NT) sWW[i * 16 + 15] = 0.f;
    if (tid < 75) sPO[tid] = (tid / 15) * PMSZ + (tid % 15);
    {
        float* sX = S + 10240;
        for (int i = tid; i < 8192; i += NT) {
            int d = i >> 6, nn = i & 63;
            sX[d * 65 + nn] = node[d * BS + b * 64 + nn];
        }
    }
    __syncthreads();

    // ---- P1: NIM ----
    float* sNIM = S;
    nim_calc8(S + 10240, sWW, sNIM, tid);
    __syncthreads();

    // ---- P2: fused K/Q/M projection + FUSED 3-way mask matmul ----
    float* sPK = S + 10240;
    float* sPQ = S + 21120;
    float* sPM = S + 32000;
    float* sK = S;
    float* sQ = S + 10240;
    float* sMSG = S + 21120;

    proj3(WKg, bKg, WQg, bQg, WMg, bMg, sNIM, sPK, sPQ, sPM, tid);
    __syncthreads();
    // fused K+Q+M maskmul: one bm read feeds all three; Q and M stores deferred
    {
        int t = tid;
        int dg = t >> 4, n0 = (t & 15) << 2;
        u64 k0[2], k1[2], k2[2], k3[2];
        u64 q0[2], q1[2], q2[2], q3[2];
        u64 g0[2], g1[2], g2[2], g3[2];
        k0[0] = k0[1] = k1[0] = k1[1] = k2[0] = k2[1] = k3[0] = k3[1] = 0ull;
        q0[0] = q0[1] = q1[0] = q1[1] = q2[0] = q2[1] = q3[0] = q3[1] = 0ull;
        g0[0] = g0[1] = g1[0] = g1[1] = g2[0] = g2[1] = g3[0] = g3[1] = 0ull;
        int r0 = dg * PSTR, r1 = (dg + 32) * PSTR, r2 = (dg + 64) * PSTR, r3 = (dg + 96) * PSTR;
        int mC[4], ddC[4], NC[4];
#pragma unroll
        for (int i = 0; i < 4; i++) {
            int f = (dg + 32 * i) * 75;
            mC[i] = f / 1920;
            int r = f - mC[i] * 1920;
            ddC[i] = r / 15;
            NC[i] = r - ddC[i] * 15;
        }
        for (int j = 0; j < 75; j++) {
            int po = sPO[j];
            ulonglong2 bm = *(const ulonglong2*)(sMask + j * 64 + n0);
            u64 sk0 = bc2(sPK[r0 + po]);
            u64 sk1 = bc2(sPK[r1 + po]);
            u64 sk2 = bc2(sPK[r2 + po]);
            u64 sk3 = bc2(sPK[r3 + po]);
            fma2(k0[0], sk0, bm.x); fma2(k0[1], sk0, bm.y);
            fma2(k1[0], sk1, bm.x); fma2(k1[1], sk1, bm.y);
            fma2(k2[0], sk2, bm.x); fma2(k2[1], sk2, bm.y);
            fma2(k3[0], sk3, bm.x); fma2(k3[1], sk3, bm.y);
            u64 sq0 = bc2(sPQ[r0 + po]);
            u64 sq1 = bc2(sPQ[r1 + po]);
            u64 sq2 = bc2(sPQ[r2 + po]);
            u64 sq3 = bc2(sPQ[r3 + po]);
            fma2(q0[0], sq0, bm.x); fma2(q0[1], sq0, bm.y);
            fma2(q1[0], sq1, bm.x); fma2(q1[1], sq1, bm.y);
            fma2(q2[0], sq2, bm.x); fma2(q2[1], sq2, bm.y);
            fma2(q3[0], sq3, bm.x); fma2(q3[1], sq3, bm.y);
            u64 sm0 = bc2(sPM[mC[0] * PMSZ + ddC[0] * PSTR + NC[0]]);
            u64 sm1 = bc2(sPM[mC[1] * PMSZ + ddC[1] * PSTR + NC[1]]);
            u64 sm2 = bc2(sPM[mC[2] * PMSZ + ddC[2] * PSTR + NC[2]]);
            u64 sm3 = bc2(sPM[mC[3] * PMSZ + ddC[3] * PSTR + NC[3]]);
            fma2(g0[0], sm0, bm.x); fma2(g0[1], sm0, bm.y);
            fma2(g1[0], sm1, bm.x); fma2(g1[1], sm1, bm.y);
            fma2(g2[0], sm2, bm.x); fma2(g2[1], sm2, bm.y);
            fma2(g3[0], sm3, bm.x); fma2(g3[1], sm3, bm.y);
#pragma unroll
            for (int i = 0; i < 4; i++) {
                if (++NC[i] == 15) {
                    NC[i] = 0;
                    if (++ddC[i] == 128) { ddC[i] = 0; ++mC[i]; }
                }
            }
        }
        *(ulonglong2*)(sK + dg * 64 + n0) = make_ulonglong2(k0[0], k0[1]);
        *(ulonglong2*)(sK + (dg + 32) * 64 + n0) = make_ulonglong2(k1[0], k1[1]);
        *(ulonglong2*)(sK + (dg + 64) * 64 + n0) = make_ulonglong2(k2[0], k2[1]);
        *(ulonglong2*)(sK + (dg + 96) * 64 + n0) = make_ulonglong2(k3[0], k3[1]);
        __syncthreads();  // all PK/PQ/PM reads done; regions reusable
        *(ulonglong2*)(sQ + dg * 64 + n0) = make_ulonglong2(q0[0], q0[1]);
        *(ulonglong2*)(sQ + (dg + 32) * 64 + n0) = make_ulonglong2(q1[0], q1[1]);
        *(ulonglong2*)(sQ + (dg + 64) * 64 + n0) = make_ulonglong2(q2[0], q2[1]);
        *(ulonglong2*)(sQ + (dg + 96) * 64 + n0) = make_ulonglong2(q3[0], q3[1]);
        *(ulonglong2*)(sMSG + dg * 64 + n0) = make_ulonglong2(g0[0], g0[1]);
        *(ulonglong2*)(sMSG + (dg + 32) * 64 + n0) = make_ulonglong2(g1[0], g1[1]);
        *(ulonglong2*)(sMSG + (dg + 64) * 64 + n0) = make_ulonglong2(g2[0], g2[1]);
        *(ulonglong2*)(sMSG + (dg + 96) * 64 + n0) = make_ulonglong2(g3[0], g3[1]);
    }
    __syncthreads();

    // ---- P3: A = Q^T K / sqrt(dk) (4-row tile), softmax(R+A) ----
    float* sA = S + 29312;
    {
        int t = tid;
        int h = t >> 7, rem = t & 127, i0r = rem >> 3, j0 = (rem & 7) << 3;
        u64 a[4][4];
#pragma unroll
        for (int c = 0; c < 4; c++)
#pragma unroll
            for (int j = 0; j < 4; j++) a[c][j] = 0ull;
        for (int k = 0; k < 32; k++) {
            const float* kr = sK + (h * 32 + k) * 64 + j0;
            const float* qr = sQ + (h * 32 + k) * 64;
            ulonglong2 nv0 = *(const ulonglong2*)(kr);
            ulonglong2 nv1 = *(const ulonglong2*)(kr + 4);
#pragma unroll
            for (int c = 0; c < 4; c++) {
                u64 qv = bc2(qr[i0r + 16 * c]);
                FMA4(a[c], qv)
            }
        }
        u64 s2 = bc2(0.17677669529663687f);
#pragma unroll
        for (int c = 0; c < 4; c++) {
#pragma unroll
            for (int j = 0; j < 4; j++) a[c][j] = mul2(a[c][j], s2);
            float* o = sA + (h * 64 + i0r + 16 * c) * 64 + j0;
            *(ulonglong2*)(o) = make_ulonglong2(a[c][0], a[c][1]);
            *(ulonglong2*)(o + 4) = make_ulonglong2(a[c][2], a[c][3]);
        }
    }
    __syncthreads();

    {
        int warp = tid >> 5, lane = tid & 31;
        for (int r = warp; r < 256; r += NT / 32) {
            float* row = sA + r * 64;
            const float* rrow = Rg + b * 16384 + r * 64;
            float v0 = row[lane] + rrow[lane];
            float v1 = row[lane + 32] + rrow[lane + 32];
            float mx = fmaxf(v0, v1);
#pragma unroll
            for (int o = 16; o > 0; o >>= 1) mx = fmaxf(mx, __shfl_xor_sync(0xffffffffu, mx, o));
            float e0 = __expf(v0 - mx), e1 = __expf(v1 - mx);
            float sum = e0 + e1;
#pragma unroll
            for (int o = 16; o > 0; o >>= 1) sum += __shfl_xor_sync(0xffffffffu, sum, o);
            float inv = 1.f / sum;
            row[lane] = e0 * inv;
            row[lane + 32] = e1 * inv;
        }
    }
    __syncthreads();

    // ---- P4 buffers ----
    float* sRES = S;            // swizzled res2 [32][256]
    float* sCpad = S + 8192;    // stride-65 gelu output
    float* sWB4 = S + 16512;    // Wmsg / ww tile
    float* sPart = S + 45696;   // 2048 split-K partials

    // aw[0,0] output (b==0) fused with head-0 Wmsg load
    if (b == 0) {
        for (int idx = tid; idx < 4096; idx += NT) {
            int ii = idx >> 6, j4 = (idx & 63) << 2;
            float4 am = *(const float4*)(AMg + ii * 256 + j4);
            float4 av = *(const float4*)(sA + ii * 64 + (j4 & 63));
            float4 o;
            o.x = av.x * am.x; o.y = av.y * am.y; o.z = av.z * am.z; o.w = av.w * am.w;
            *(float4*)(outp + D * BS + ii * 256 + j4) = o;
        }
    }
    load_wmsg(sWB4, Wup, Wdn, Wlf, Wrt, tid);
    __syncthreads();

    // ---- P4: per-head res + masked attention apply + gelu -> Cpad ----
    for (int h = 0; h < 4; h++) {
        // RES (512 threads, 4q x 4n) -> swizzled res2
        {
            int qg = tid >> 4;
            int n0 = (tid & 15) << 2;
            u64 c[4][2];
#pragma unroll
            for (int s = 0; s < 4; s++) { c[s][0] = 0ull; c[s][1] = 0ull; }
            for (int kk = 0; kk < 32; kk++) {
                const float* mr = sMSG + (h * 32 + kk) * 64 + n0;
                ulonglong2 nv = *(const ulonglong2*)(mr);
#pragma unroll
                for (int s = 0; s < 4; s++) {
                    int q = qg + 32 * s;
                    u64 w = bc2(sWB4[(q << 5) + ((kk + q) & 31)]);
                    fma2(c[s][0], w, nv.x);
                    fma2(c[s][1], w, nv.y);
                }
            }
#pragma unroll
            for (int s = 0; s < 4; s++) {
                int q = qg + 32 * s;
                int kq = q >> 2;
                int off = ((q & 3) << 6) + n0;
                int sw = (kq & 7) << 2;
                *(ulonglong2*)(sRES + (kq << 8) + (off ^ sw)) =
                    make_ulonglong2(c[s][0], c[s][1]);
            }
        }
        __syncthreads();  // RES done; sWB4 (Wmsg) free to become ww
        stage1_ww(sA, AMg, sWB4, h, 0, tid);
        __syncthreads();

        for (int i0 = 0; i0 < 64; i0 += 16) {
            // stage2: 4-way split-K x 2 ii-halves across 8 warps, 4k x 2ii tiles
            if (tid < 256) {
                int warp = tid >> 5;
                int g = warp & 3;        // j2 quarter
                int half = warp >> 2;    // ii half
                int r = tid & 31;
                int kp = r >> 2;         // 0..7
                int iip = r & 3;         // 0..3
                int jbase = g << 6;
                int ksw = kp << 2;
                int iiA = half * 8 + iip;
                int iiB = iiA + 4;
                const float* wA = sWB4 + (iiA << 8);
                const float* wB = sWB4 + (iiB << 8);
                int swA = iiA << 2, swB = iiB << 2;
                u64 acc[4][2];
#pragma unroll
                for (int c = 0; c < 4; c++) { acc[c][0] = 0ull; acc[c][1] = 0ull; }
#pragma unroll 4
                for (int jj = 0; jj < 64; jj += 4) {
                    int j2 = jbase + jj;
                    int jx = j2 ^ ksw;
                    ulonglong2 rv[4];
#pragma unroll
                    for (int c = 0; c < 4; c++)
                        rv[c] = *(const ulonglong2*)(sRES + ((kp + 8 * c) << 8) + jx);
                    ulonglong2 wvA = *(const ulonglong2*)(wA + (j2 ^ swA));
                    ulonglong2 wvB = *(const ulonglong2*)(wB + (j2 ^ swB));
#pragma unroll
                    for (int c = 0; c < 4; c++) {
                        fma2(acc[c][0], rv[c].x, wvA.x);
                        fma2(acc[c][0], rv[c].y, wvA.y);
                        fma2(acc[c][1], rv[c].x, wvB.x);
                        fma2(acc[c][1], rv[c].y, wvB.y);
                    }
                }
                int gb = g << 9;
#pragma unroll
                for (int c = 0; c < 4; c++) {
                    int k = kp + 8 * c;
                    sPart[gb + (k << 4) + iiA] = hsum2(acc[c][0]);
                    sPart[gb + (k << 4) + iiB] = hsum2(acc[c][1]);
                }
            }
            __syncthreads();
            // stage3: reduce + gelu -> Cpad ; fused with stage1(next) or Wmsg(next head)
            {
                float v = sPart[tid] + sPart[512 + tid] + sPart[1024 + tid] + sPart[1536 + tid];
                int k = tid >> 4, ii = tid & 15;
                sCpad[(h * 32 + k) * 65 + i0 + ii] = gelu_exact(v);
            }
            if (i0 < 48) {
                stage1_ww(sA, AMg, sWB4, h, i0 + 16, tid);
            } else if (h < 3) {
                load_wmsg(sWB4, Wup, Wdn, Wlf, Wrt, tid);
            }
            __syncthreads();
        }
    }

    // ---- P5: back-projection + residual (Cpad already stride-65) ----
    float* sNIM2 = S + 16512;
    nim_calc8(sCpad, sWW, sNIM2, tid);
    __syncthreads();
    float* sPB = S;
    proj1(WBg, bBg, sNIM2, sPB, tid);
    __syncthreads();

    for (int t = tid; t < 512; t += NT) {
        int dg = t >> 4, n0 = (t & 15) << 2;
        u64 a0[2], a1[2], a2[2], a3[2];
        a0[0] = a0[1] = a1[0] = a1[1] = a2[0] = a2[1] = a3[0] = a3[1] = 0ull;
        const float* p0 = sPB + dg * PSTR;
        const float* p1 = sPB + (dg + 32) * PSTR;
        const float* p2 = sPB + (dg + 64) * PSTR;
        const float* p3 = sPB + (dg + 96) * PSTR;
        for (int j = 0; j < 75; j++) {
            int po = sPO[j];
            u64 s0 = bc2(p0[po]);
            u64 s1 = bc2(p1[po]);
            u64 s2 = bc2(p2[po]);
            u64 s3 = bc2(p3[po]);
            ulonglong2 bm = *(const ulonglong2*)(sMask + j * 64 + n0);
            fma2(a0[0], s0, bm.x); fma2(a0[1], s0, bm.y);
            fma2(a1[0], s1, bm.x); fma2(a1[1], s1, bm.y);
            fma2(a2[0], s2, bm.x); fma2(a2[1], s2, bm.y);
            fma2(a3[0], s3, bm.x); fma2(a3[1], s3, bm.y);
        }
#pragma unroll
        for (int i = 0; i < 4; i++) {
            const u64* acc = (i == 0) ? a0 : (i == 1) ? a1 : (i == 2) ? a2 : a3;
            int d = dg + 32 * i;
            int gi = d * BS + b * 64 + n0;
            ulonglong2 rr = *(const ulonglong2*)(node + gi);
            *(ulonglong2*)(outp + gi) =
                make_ulonglong2(add2(acc[0], rr.x), add2(acc[1], rr.y));
        }
    }
}

extern "C" void kernel_launch(void* const* d_in, const int* in_sizes, int n_in,
                              void* d_out, int out_size) {
    const float* node = (const float*)d_in[0];
    const float* WWg = (const float*)d_in[1];
    const float* maskg = (const float*)d_in[2];
    const float* Rg = (const float*)d_in[3];
    const float* AMg = (const float*)d_in[4];
    const float* WKg = (const float*)d_in[5];
    const float* bKg = (const float*)d_in[6];
    const float* WQg = (const float*)d_in[7];
    const float* bQg = (const float*)d_in[8];
    const float* WMg = (const float*)d_in[9];
    const float* bMg = (const float*)d_in[10];
    const float* WBg = (const float*)d_in[11];
    const float* bBg = (const float*)d_in[12];
    const float* Wup = (const float*)d_in[13];
    const float* Wdn = (const float*)d_in[14];
    const float* Wlf = (const float*)d_in[15];
    const float* Wrt = (const float*)d_in[16];
    float* outp = (float*)d_out;

    int nb = in_sizes[0] / (D * NV);
    size_t smem = SMEM_FLOATS * sizeof(float);
    cudaFuncSetAttribute(hgt_kernel, cudaFuncAttributeMaxDynamicSharedMemorySize, (int)smem);
    hgt_kernel<<<nb, NT, smem>>>(node, WWg, maskg, Rg, AMg, WKg, bKg, WQg, bQg,
                                 WMg, bMg, WBg, bBg, Wup, Wdn, Wlf, Wrt, outp, nb);
}

// round 14
// speedup vs baseline: 1.0676x; 1.0440x over previous
#include <cuda_runtime.h>
#include <math.h>

#define NT 512
#define D 128
#define H 4
#define DK 32
#define M 5
#define NN 15
#define NV 64
#define PSTR 17            // padded stride for P buffers
#define PMSZ (128 * PSTR)  // 2176 floats per type

// ---------------- shared memory layout (floats) ----------------
// sm[0..4800)     : sMask (persistent)
// sm[4800..9920)  : sWW   (persistent, padded (5,64,16))
// sm[9920..10048) : sPO offset table
// S = sm + 10048, extent 47744:
//  P0/P1: Xpad S[10240..18560) stride-65 ; NIM S[0..10240)
//  P2   : PK S[10240..21120), PQ S[21120..32000), PM S[32000..42880)
//         K -> S[0..8192), Q -> S[10240..18432), MSG -> S[21120..29312)
//  P3   : A/aw -> S[29312..45696)  (softmax fused into QK^T epilogue)
//  P4   : RES S[0..8192) (swizzled res2), Cpad S[8192..16512) stride-65,
//         Wmsg/ww S[16512..20608), sPart S[45696..47744); MSG + sA alive
//  P5   : NIM2 S[16512..26752), PB S[0..10880)  (Cpad read by nim)
#define SMEM_FLOATS (10048 + 47744)

typedef unsigned long long u64;

static __device__ __forceinline__ u64 bc2(float v) {
    u64 r; asm("mov.b64 %0, {%1, %1};" : "=l"(r) : "f"(v)); return r;
}
static __device__ __forceinline__ void fma2(u64& d, u64 a, u64 b) {
    asm("fma.rn.f32x2 %0, %1, %2, %0;" : "+l"(d) : "l"(a), "l"(b));
}
static __device__ __forceinline__ u64 add2(u64 a, u64 b) {
    u64 r; asm("add.rn.f32x2 %0, %1, %2;" : "=l"(r) : "l"(a), "l"(b)); return r;
}
static __device__ __forceinline__ u64 mul2(u64 a, u64 b) {
    u64 r; asm("mul.rn.f32x2 %0, %1, %2;" : "=l"(r) : "l"(a), "l"(b)); return r;
}
static __device__ __forceinline__ void unpk(u64 v, float& lo, float& hi) {
    asm("mov.b64 {%0, %1}, %2;" : "=f"(lo), "=f"(hi) : "l"(v));
}
static __device__ __forceinline__ float hsum2(u64 v) {
    float lo, hi; unpk(v, lo, hi); return lo + hi;
}
static __device__ __forceinline__ float gelu_exact(float x) {
    return 0.5f * x * (1.f + erff(x * 0.70710678118654752f));
}

// NIM[m][dd][n0..+3] = sum_nn In[dd][nn] * WW[m][nn][n0..]; 8-row x 4-col tile
static __device__ __forceinline__ void nim_calc8(const float* __restrict__ sIn /*stride65*/,
                                                 const float* __restrict__ sWW,
                                                 float* __restrict__ sNIM, int tid) {
    for (int t = tid; t < 320; t += NT) {
        int m = t >> 6;
        int r = t & 63;
        int dd0 = (r >> 2) << 3;
        int n0 = (r & 3) << 2;
        const float* xb = sIn + dd0 * 65;
        const float* wb = sWW + m * 1024 + n0;
        u64 a[8][2];
#pragma unroll
        for (int i = 0; i < 8; i++) { a[i][0] = 0ull; a[i][1] = 0ull; }
#pragma unroll 4
        for (int nn = 0; nn < 64; nn++) {
            ulonglong2 w = *(const ulonglong2*)(wb + nn * 16);
#pragma unroll
            for (int i = 0; i < 8; i++) {
                u64 v = bc2(xb[i * 65 + nn]);
                fma2(a[i][0], v, w.x);
                fma2(a[i][1], v, w.y);
            }
        }
        float* o = sNIM + m * 2048 + dd0 * 16 + n0;
#pragma unroll
        for (int i = 0; i < 8; i++)
            *(ulonglong2*)(o + i * 16) = make_ulonglong2(a[i][0], a[i][1]);
    }
}

#define FMA4(acc, wb_)                       \
    fma2(acc[0], wb_, nv0.x); fma2(acc[1], wb_, nv0.y); \
    fma2(acc[2], wb_, nv1.x); fma2(acc[3], wb_, nv1.y);

static __device__ __forceinline__ void store8(float* __restrict__ P, int o, const u64* acc, float bias) {
#pragma unroll
    for (int p = 0; p < 4; p++) {
        float lo, hi; unpk(acc[p], lo, hi);
        P[o + 2 * p] = lo + bias;
        P[o + 2 * p + 1] = hi + bias;
    }
}

// Fused K/Q/M projection: 2-row tile (dd, dd+64), j-split 2, f32x2
static __device__ __forceinline__ void proj3(const float* __restrict__ WK, const float* __restrict__ bK,
                                             const float* __restrict__ WQ, const float* __restrict__ bQ,
                                             const float* __restrict__ WM, const float* __restrict__ bM,
                                             const float* __restrict__ sNIM,
                                             float* __restrict__ PK, float* __restrict__ PQ,
                                             float* __restrict__ PM, int tid) {
    for (int t = tid; t < 640; t += NT) {
        int pairidx = t >> 1;
        int j0 = (t & 1) << 3;
        int m = pairidx >> 6;
        int dd0 = pairidx & 63;
        const float* nb = sNIM + m * 2048 + j0;
        int ro0 = (m * 128 + dd0) * 128;
        int ro1 = ro0 + 64 * 128;
        u64 aK0[4], aK1[4], aQ0[4], aQ1[4], aM0[4], aM1[4];
#pragma unroll
        for (int j = 0; j < 4; j++) {
            aK0[j] = aK1[j] = aQ0[j] = aQ1[j] = aM0[j] = aM1[j] = 0ull;
        }
        for (int e4 = 0; e4 < 128; e4 += 4) {
            float4 wK0 = *(const float4*)(WK + ro0 + e4);
            float4 wK1 = *(const float4*)(WK + ro1 + e4);
            float4 wQ0 = *(const float4*)(WQ + ro0 + e4);
            float4 wQ1 = *(const float4*)(WQ + ro1 + e4);
            float4 wM0 = *(const float4*)(WM + ro0 + e4);
            float4 wM1 = *(const float4*)(WM + ro1 + e4);
#pragma unroll
            for (int u = 0; u < 4; u++) {
                ulonglong2 nv0 = *(const ulonglong2*)(nb + (e4 + u) * 16);
                ulonglong2 nv1 = *(const ulonglong2*)(nb + (e4 + u) * 16 + 4);
                u64 bk0 = bc2(((const float*)&wK0)[u]);
                u64 bk1 = bc2(((const float*)&wK1)[u]);
                u64 bq0 = bc2(((const float*)&wQ0)[u]);
                u64 bq1 = bc2(((const float*)&wQ1)[u]);
                u64 bm0 = bc2(((const float*)&wM0)[u]);
                u64 bm1 = bc2(((const float*)&wM1)[u]);
                FMA4(aK0, bk0) FMA4(aK1, bk1)
                FMA4(aQ0, bq0) FMA4(aQ1, bq1)
                FMA4(aM0, bm0) FMA4(aM1, bm1)
            }
        }
        int o0 = m * PMSZ + dd0 * PSTR + j0;
        int o1 = o0 + 64 * PSTR;
        store8(PK, o0, aK0, bK[m * 128 + dd0]);
        store8(PK, o1, aK1, bK[m * 128 + dd0 + 64]);
        store8(PQ, o0, aQ0, bQ[m * 128 + dd0]);
        store8(PQ, o1, aQ1, bQ[m * 128 + dd0 + 64]);
        store8(PM, o0, aM0, bM[m * 128 + dd0]);
        store8(PM, o1, aM1, bM[m * 128 + dd0 + 64]);
    }
}

// single projection (WB): 4-row tile, j-split 2, f32x2
static __device__ __forceinline__ void proj1(const float* __restrict__ W, const float* __restrict__ bg,
                                             const float* __restrict__ sNIM, float* __restrict__ P,
                                             int tid) {
    for (int t = tid; t < 320; t += NT) {
        int gidx = t >> 1;
        int j0 = (t & 1) << 3;
        int m = gidx >> 5;
        int dd0 = gidx & 31;
        const float* nb = sNIM + m * 2048 + j0;
        int ro[4];
#pragma unroll
        for (int i = 0; i < 4; i++) ro[i] = (m * 128 + dd0 + 32 * i) * 128;
        u64 a0[4], a1[4], a2[4], a3[4];
#pragma unroll
        for (int j = 0; j < 4; j++) { a0[j] = a1[j] = a2[j] = a3[j] = 0ull; }
        for (int e4 = 0; e4 < 128; e4 += 4) {
            float4 w0 = *(const float4*)(W + ro[0] + e4);
            float4 w1 = *(const float4*)(W + ro[1] + e4);
            float4 w2 = *(const float4*)(W + ro[2] + e4);
            float4 w3 = *(const float4*)(W + ro[3] + e4);
#pragma unroll
            for (int u = 0; u < 4; u++) {
                ulonglong2 nv0 = *(const ulonglong2*)(nb + (e4 + u) * 16);
                ulonglong2 nv1 = *(const ulonglong2*)(nb + (e4 + u) * 16 + 4);
                u64 b0 = bc2(((const float*)&w0)[u]);
                u64 b1 = bc2(((const float*)&w1)[u]);
                u64 b2 = bc2(((const float*)&w2)[u]);
                u64 b3 = bc2(((const float*)&w3)[u]);
                FMA4(a0, b0) FMA4(a1, b1) FMA4(a2, b2) FMA4(a3, b3)
            }
        }
#pragma unroll
        for (int i = 0; i < 4; i++) {
            const u64* acc = (i == 0) ? a0 : (i == 1) ? a1 : (i == 2) ? a2 : a3;
            int o = m * PMSZ + (dd0 + 32 * i) * PSTR + j0;
            store8(P, o, acc, bg[m * 128 + dd0 + 32 * i]);
        }
    }
}

// stage1: ww[ii][j] = aw[h][i0+ii][j%64] * AM[i0+ii][j], XOR-swizzled; 1024 items
static __device__ __forceinline__ void stage1_ww(const float* __restrict__ sA,
                                                 const float* __restrict__ AMg,
                                                 float* __restrict__ sWB4,
                                                 int h, int i0, int tid) {
#pragma unroll
    for (int rep = 0; rep < 2; rep++) {
        int idx = tid + rep * NT;
        int ii = idx >> 6;
        int j4 = (idx & 63) << 2;
        int i = i0 + ii;
        float4 am = *(const float4*)(AMg + i * 256 + j4);
        float4 av = *(const float4*)(sA + (h * 64 + i) * 64 + (j4 & 63));
        float4 w;
        w.x = av.x * am.x; w.y = av.y * am.y; w.z = av.z * am.z; w.w = av.w * am.w;
        *(float4*)(sWB4 + ii * 256 + (j4 ^ (ii << 2))) = w;
    }
}

// Wmsg load (head-independent), swizzled [q][(kk+q)&31]
static __device__ __forceinline__ void load_wmsg(float* __restrict__ sWB4,
                                                 const float* __restrict__ Wup,
                                                 const float* __restrict__ Wdn,
                                                 const float* __restrict__ Wlf,
                                                 const float* __restrict__ Wrt, int tid) {
#pragma unroll
    for (int rep = 0; rep < 8; rep++) {
        int i = tid + rep * NT;
        int q = i >> 5, kk = i & 31;
        int dir = q >> 5, col = q & 31;
        const float* Wd = (dir == 0) ? Wup : (dir == 1) ? Wdn : (dir == 2) ? Wlf : Wrt;
        sWB4[(q << 5) + ((kk + q) & 31)] = Wd[kk * 32 + col];
    }
}

__global__ void __launch_bounds__(NT, 1)
hgt_kernel(const float* __restrict__ node, const float* __restrict__ WWg,
           const float* __restrict__ maskg, const float* __restrict__ Rg,
           const float* __restrict__ AMg,
           const float* __restrict__ WKg, const float* __restrict__ bKg,
           const float* __restrict__ WQg, const float* __restrict__ bQg,
           const float* __restrict__ WMg, const float* __restrict__ bMg,
           const float* __restrict__ WBg, const float* __restrict__ bBg,
           const float* __restrict__ Wup, const float* __restrict__ Wdn,
           const float* __restrict__ Wlf, const float* __restrict__ Wrt,
           float* __restrict__ outp, int nb) {
    const int b = blockIdx.x;
    const int tid = threadIdx.x;
    const int BS = nb * NV;
    extern __shared__ float sm[];
    float* sMask = sm;
    float* sWW = sm + 4800;
    int* sPO = (int*)(sm + 9920);
    float* S = sm + 10048;

    // ---- P0: loads ----
    for (int i = tid; i < 4800; i += NT) sMask[i] = maskg[i];
    for (int i = tid; i < 4800; i += NT) {
        int m = i / 960;
        int r = i - m * 960;
        int nn = r / 15;
        int N = r - nn * 15;
        sWW[m * 1024 + nn * 16 + N] = WWg[b * 4800 + i];
    }
    for (int i = tid; i < 320; i += NT) sWW[i * 16 + 15] = 0.f;
    if (tid < 75) sPO[tid] = (tid / 15) * PMSZ + (tid % 15);
    {
        float* sX = S + 10240;
        for (int i = tid; i < 8192; i += NT) {
            int d = i >> 6, nn = i & 63;
            sX[d * 65 + nn] = node[d * BS + b * 64 + nn];
        }
    }
    __syncthreads();

    // ---- P1: NIM ----
    float* sNIM = S;
    nim_calc8(S + 10240, sWW, sNIM, tid);
    __syncthreads();

    // ---- P2: fused K/Q/M projection + FUSED 3-way mask matmul ----
    float* sPK = S + 10240;
    float* sPQ = S + 21120;
    float* sPM = S + 32000;
    float* sK = S;
    float* sQ = S + 10240;
    float* sMSG = S + 21120;

    proj3(WKg, bKg, WQg, bQg, WMg, bMg, sNIM, sPK, sPQ, sPM, tid);
    __syncthreads();
    // fused K+Q+M maskmul: one bm read feeds all three; Q and M stores deferred
    {
        int t = tid;
        int dg = t >> 4, n0 = (t & 15) << 2;
        u64 k0[2], k1[2], k2[2], k3[2];
        u64 q0[2], q1[2], q2[2], q3[2];
        u64 g0[2], g1[2], g2[2], g3[2];
        k0[0] = k0[1] = k1[0] = k1[1] = k2[0] = k2[1] = k3[0] = k3[1] = 0ull;
        q0[0] = q0[1] = q1[0] = q1[1] = q2[0] = q2[1] = q3[0] = q3[1] = 0ull;
        g0[0] = g0[1] = g1[0] = g1[1] = g2[0] = g2[1] = g3[0] = g3[1] = 0ull;
        int r0 = dg * PSTR, r1 = (dg + 32) * PSTR, r2 = (dg + 64) * PSTR, r3 = (dg + 96) * PSTR;
        int mC[4], ddC[4], NC[4];
#pragma unroll
        for (int i = 0; i < 4; i++) {
            int f = (dg + 32 * i) * 75;
            mC[i] = f / 1920;
            int r = f - mC[i] * 1920;
            ddC[i] = r / 15;
            NC[i] = r - ddC[i] * 15;
        }
        for (int j = 0; j < 75; j++) {
            int po = sPO[j];
            ulonglong2 bm = *(const ulonglong2*)(sMask + j * 64 + n0);
            u64 sk0 = bc2(sPK[r0 + po]);
            u64 sk1 = bc2(sPK[r1 + po]);
            u64 sk2 = bc2(sPK[r2 + po]);
            u64 sk3 = bc2(sPK[r3 + po]);
            fma2(k0[0], sk0, bm.x); fma2(k0[1], sk0, bm.y);
            fma2(k1[0], sk1, bm.x); fma2(k1[1], sk1, bm.y);
            fma2(k2[0], sk2, bm.x); fma2(k2[1], sk2, bm.y);
            fma2(k3[0], sk3, bm.x); fma2(k3[1], sk3, bm.y);
            u64 sq0 = bc2(sPQ[r0 + po]);
            u64 sq1 = bc2(sPQ[r1 + po]);
            u64 sq2 = bc2(sPQ[r2 + po]);
            u64 sq3 = bc2(sPQ[r3 + po]);
            fma2(q0[0], sq0, bm.x); fma2(q0[1], sq0, bm.y);
            fma2(q1[0], sq1, bm.x); fma2(q1[1], sq1, bm.y);
            fma2(q2[0], sq2, bm.x); fma2(q2[1], sq2, bm.y);
            fma2(q3[0], sq3, bm.x); fma2(q3[1], sq3, bm.y);
            u64 sm0 = bc2(sPM[mC[0] * PMSZ + ddC[0] * PSTR + NC[0]]);
            u64 sm1 = bc2(sPM[mC[1] * PMSZ + ddC[1] * PSTR + NC[1]]);
            u64 sm2 = bc2(sPM[mC[2] * PMSZ + ddC[2] * PSTR + NC[2]]);
            u64 sm3 = bc2(sPM[mC[3] * PMSZ + ddC[3] * PSTR + NC[3]]);
            fma2(g0[0], sm0, bm.x); fma2(g0[1], sm0, bm.y);
            fma2(g1[0], sm1, bm.x); fma2(g1[1], sm1, bm.y);
            fma2(g2[0], sm2, bm.x); fma2(g2[1], sm2, bm.y);
            fma2(g3[0], sm3, bm.x); fma2(g3[1], sm3, bm.y);
#pragma unroll
            for (int i = 0; i < 4; i++) {
                if (++NC[i] == 15) {
                    NC[i] = 0;
                    if (++ddC[i] == 128) { ddC[i] = 0; ++mC[i]; }
                }
            }
        }
        *(ulonglong2*)(sK + dg * 64 + n0) = make_ulonglong2(k0[0], k0[1]);
        *(ulonglong2*)(sK + (dg + 32) * 64 + n0) = make_ulonglong2(k1[0], k1[1]);
        *(ulonglong2*)(sK + (dg + 64) * 64 + n0) = make_ulonglong2(k2[0], k2[1]);
        *(ulonglong2*)(sK + (dg + 96) * 64 + n0) = make_ulonglong2(k3[0], k3[1]);
        __syncthreads();  // all PK/PQ/PM reads done; regions reusable
        *(ulonglong2*)(sQ + dg * 64 + n0) = make_ulonglong2(q0[0], q0[1]);
        *(ulonglong2*)(sQ + (dg + 32) * 64 + n0) = make_ulonglong2(q1[0], q1[1]);
        *(ulonglong2*)(sQ + (dg + 64) * 64 + n0) = make_ulonglong2(q2[0], q2[1]);
        *(ulonglong2*)(sQ + (dg + 96) * 64 + n0) = make_ulonglong2(q3[0], q3[1]);
        *(ulonglong2*)(sMSG + dg * 64 + n0) = make_ulonglong2(g0[0], g0[1]);
        *(ulonglong2*)(sMSG + (dg + 32) * 64 + n0) = make_ulonglong2(g1[0], g1[1]);
        *(ulonglong2*)(sMSG + (dg + 64) * 64 + n0) = make_ulonglong2(g2[0], g2[1]);
        *(ulonglong2*)(sMSG + (dg + 96) * 64 + n0) = make_ulonglong2(g3[0], g3[1]);
    }
    __syncthreads();

    // ---- P3: A = Q^T K / sqrt(dk) with FUSED R-add + softmax epilogue ----
    // Each row of A (64 cols) lives in 8 consecutive lanes (8 cols each):
    // reduce max/sum via shfl_xor 1/2/4 within the 8-lane group, write aw.
    float* sA = S + 29312;
    {
        int t = tid;
        int h = t >> 7, rem = t & 127, i0r = rem >> 3, j0 = (rem & 7) << 3;
        u64 a[4][4];
#pragma unroll
        for (int c = 0; c < 4; c++)
#pragma unroll
            for (int j = 0; j < 4; j++) a[c][j] = 0ull;
        for (int k = 0; k < 32; k++) {
            const float* kr = sK + (h * 32 + k) * 64 + j0;
            const float* qr = sQ + (h * 32 + k) * 64;
            ulonglong2 nv0 = *(const ulonglong2*)(kr);
            ulonglong2 nv1 = *(const ulonglong2*)(kr + 4);
#pragma unroll
            for (int c = 0; c < 4; c++) {
                u64 qv = bc2(qr[i0r + 16 * c]);
                FMA4(a[c], qv)
            }
        }
        const float s = 0.17677669529663687f;  // 1/sqrt(32)
#pragma unroll
        for (int c = 0; c < 4; c++) {
            int i = i0r + 16 * c;
            const float* rr = Rg + b * 16384 + (h * 64 + i) * 64 + j0;
            float4 rv0 = *(const float4*)(rr);
            float4 rv1 = *(const float4*)(rr + 4);
            float v[8];
            {
                float lo, hi;
                unpk(a[c][0], lo, hi); v[0] = lo * s + rv0.x; v[1] = hi * s + rv0.y;
                unpk(a[c][1], lo, hi); v[2] = lo * s + rv0.z; v[3] = hi * s + rv0.w;
                unpk(a[c][2], lo, hi); v[4] = lo * s + rv1.x; v[5] = hi * s + rv1.y;
                unpk(a[c][3], lo, hi); v[6] = lo * s + rv1.z; v[7] = hi * s + rv1.w;
            }
            float mx = v[0];
#pragma unroll
            for (int j = 1; j < 8; j++) mx = fmaxf(mx, v[j]);
            mx = fmaxf(mx, __shfl_xor_sync(0xffffffffu, mx, 1));
            mx = fmaxf(mx, __shfl_xor_sync(0xffffffffu, mx, 2));
            mx = fmaxf(mx, __shfl_xor_sync(0xffffffffu, mx, 4));
            float sum = 0.f;
#pragma unroll
            for (int j = 0; j < 8; j++) { v[j] = __expf(v[j] - mx); sum += v[j]; }
            sum += __shfl_xor_sync(0xffffffffu, sum, 1);
            sum += __shfl_xor_sync(0xffffffffu, sum, 2);
            sum += __shfl_xor_sync(0xffffffffu, sum, 4);
            float inv = 1.f / sum;
            float4 o0, o1;
            o0.x = v[0] * inv; o0.y = v[1] * inv; o0.z = v[2] * inv; o0.w = v[3] * inv;
            o1.x = v[4] * inv; o1.y = v[5] * inv; o1.z = v[6] * inv; o1.w = v[7] * inv;
            float* op = sA + (h * 64 + i) * 64 + j0;
            *(float4*)(op) = o0;
            *(float4*)(op + 4) = o1;
        }
    }
    __syncthreads();

    // ---- P4 buffers ----
    float* sRES = S;            // swizzled res2 [32][256]
    float* sCpad = S + 8192;    // stride-65 gelu output
    float* sWB4 = S + 16512;    // Wmsg / ww tile
    float* sPart = S + 45696;   // 2048 split-K partials

    // aw[0,0] output (b==0) fused with head-0 Wmsg load
    if (b == 0) {
        for (int idx = tid; idx < 4096; idx += NT) {
            int ii = idx >> 6, j4 = (idx & 63) << 2;
            float4 am = *(const float4*)(AMg + ii * 256 + j4);
            float4 av = *(const float4*)(sA + ii * 64 + (j4 & 63));
            float4 o;
            o.x = av.x * am.x; o.y = av.y * am.y; o.z = av.z * am.z; o.w = av.w * am.w;
            *(float4*)(outp + D * BS + ii * 256 + j4) = o;
        }
    }
    load_wmsg(sWB4, Wup, Wdn, Wlf, Wrt, tid);
    __syncthreads();

    // ---- P4: per-head res + masked attention apply + gelu -> Cpad ----
    for (int h = 0; h < 4; h++) {
        // RES (512 threads, 4q x 4n) -> swizzled res2
        {
            int qg = tid >> 4;
            int n0 = (tid & 15) << 2;
            u64 c[4][2];
#pragma unroll
            for (int s = 0; s < 4; s++) { c[s][0] = 0ull; c[s][1] = 0ull; }
            for (int kk = 0; kk < 32; kk++) {
                const float* mr = sMSG + (h * 32 + kk) * 64 + n0;
                ulonglong2 nv = *(const ulonglong2*)(mr);
#pragma unroll
                for (int s = 0; s < 4; s++) {
                    int q = qg + 32 * s;
                    u64 w = bc2(sWB4[(q << 5) + ((kk + q) & 31)]);
                    fma2(c[s][0], w, nv.x);
                    fma2(c[s][1], w, nv.y);
                }
            }
#pragma unroll
            for (int s = 0; s < 4; s++) {
                int q = qg + 32 * s;
                int kq = q >> 2;
                int off = ((q & 3) << 6) + n0;
                int sw = (kq & 7) << 2;
                *(ulonglong2*)(sRES + (kq << 8) + (off ^ sw)) =
                    make_ulonglong2(c[s][0], c[s][1]);
            }
        }
        __syncthreads();  // RES done; sWB4 (Wmsg) free to become ww
        stage1_ww(sA, AMg, sWB4, h, 0, tid);
        __syncthreads();

        for (int i0 = 0; i0 < 64; i0 += 16) {
            // stage2: 4-way split-K x 2 ii-halves across 8 warps, 4k x 2ii tiles
            if (tid < 256) {
                int warp = tid >> 5;
                int g = warp & 3;        // j2 quarter
                int half = warp >> 2;    // ii half
                int r = tid & 31;
                int kp = r >> 2;         // 0..7
                int iip = r & 3;         // 0..3
                int jbase = g << 6;
                int ksw = kp << 2;
                int iiA = half * 8 + iip;
                int iiB = iiA + 4;
                const float* wA = sWB4 + (iiA << 8);
                const float* wB = sWB4 + (iiB << 8);
                int swA = iiA << 2, swB = iiB << 2;
                u64 acc[4][2];
#pragma unroll
                for (int c = 0; c < 4; c++) { acc[c][0] = 0ull; acc[c][1] = 0ull; }
#pragma unroll 4
                for (int jj = 0; jj < 64; jj += 4) {
                    int j2 = jbase + jj;
                    int jx = j2 ^ ksw;
                    ulonglong2 rv[4];
#pragma unroll
                    for (int c = 0; c < 4; c++)
                        rv[c] = *(const ulonglong2*)(sRES + ((kp + 8 * c) << 8) + jx);
                    ulonglong2 wvA = *(const ulonglong2*)(wA + (j2 ^ swA));
                    ulonglong2 wvB = *(const ulonglong2*)(wB + (j2 ^ swB));
#pragma unroll
                    for (int c = 0; c < 4; c++) {
                        fma2(acc[c][0], rv[c].x, wvA.x);
                        fma2(acc[c][0], rv[c].y, wvA.y);
                        fma2(acc[c][1], rv[c].x, wvB.x);
                        fma2(acc[c][1], rv[c].y, wvB.y);
                    }
                }
                int gb = g << 9;
#pragma unroll
                for (int c = 0; c < 4; c++) {
                    int k = kp + 8 * c;
                    sPart[gb + (k << 4) + iiA] = hsum2(acc[c][0]);
                    sPart[gb + (k << 4) + iiB] = hsum2(acc[c][1]);
                }
            }
            __syncthreads();
            // stage3: reduce + gelu -> Cpad ; fused with stage1(next) or Wmsg(next head)
            {
                float v = sPart[tid] + sPart[512 + tid] + sPart[1024 + tid] + sPart[1536 + tid];
                int k = tid >> 4, ii = tid & 15;
                sCpad[(h * 32 + k) * 65 + i0 + ii] = gelu_exact(v);
            }
            if (i0 < 48) {
                stage1_ww(sA, AMg, sWB4, h, i0 + 16, tid);
            } else if (h < 3) {
                load_wmsg(sWB4, Wup, Wdn, Wlf, Wrt, tid);
            }
            __syncthreads();
        }
    }

    // ---- P5: back-projection + residual (Cpad already stride-65) ----
    float* sNIM2 = S + 16512;
    nim_calc8(sCpad, sWW, sNIM2, tid);
    __syncthreads();
    float* sPB = S;
    proj1(WBg, bBg, sNIM2, sPB, tid);
    __syncthreads();

    for (int t = tid; t < 512; t += NT) {
        int dg = t >> 4, n0 = (t & 15) << 2;
        u64 a0[2], a1[2], a2[2], a3[2];
        a0[0] = a0[1] = a1[0] = a1[1] = a2[0] = a2[1] = a3[0] = a3[1] = 0ull;
        const float* p0 = sPB + dg * PSTR;
        const float* p1 = sPB + (dg + 32) * PSTR;
        const float* p2 = sPB + (dg + 64) * PSTR;
        const float* p3 = sPB + (dg + 96) * PSTR;
        for (int j = 0; j < 75; j++) {
            int po = sPO[j];
            u64 s0 = bc2(p0[po]);
            u64 s1 = bc2(p1[po]);
            u64 s2 = bc2(p2[po]);
            u64 s3 = bc2(p3[po]);
            ulonglong2 bm = *(const ulonglong2*)(sMask + j * 64 + n0);
            fma2(a0[0], s0, bm.x); fma2(a0[1], s0, bm.y);
            fma2(a1[0], s1, bm.x); fma2(a1[1], s1, bm.y);
            fma2(a2[0], s2, bm.x); fma2(a2[1], s2, bm.y);
            fma2(a3[0], s3, bm.x); fma2(a3[1], s3, bm.y);
        }
#pragma unroll
        for (int i = 0; i < 4; i++) {
            const u64* acc = (i == 0) ? a0 : (i == 1) ? a1 : (i == 2) ? a2 : a3;
            int d = dg + 32 * i;
            int gi = d * BS + b * 64 + n0;
            ulonglong2 rr = *(const ulonglong2*)(node + gi);
            *(ulonglong2*)(outp + gi) =
                make_ulonglong2(add2(acc[0], rr.x), add2(acc[1], rr.y));
        }
    }
}

extern "C" void kernel_launch(void* const* d_in, const int* in_sizes, int n_in,
                              void* d_out, int out_size) {
    const float* node = (const float*)d_in[0];
    const float* WWg = (const float*)d_in[1];
    const float* maskg = (const float*)d_in[2];
    const float* Rg = (const float*)d_in[3];
    const float* AMg = (const float*)d_in[4];
    const float* WKg = (const float*)d_in[5];
    const float* bKg = (const float*)d_in[6];
    const float* WQg = (const float*)d_in[7];
    const float* bQg = (const float*)d_in[8];
    const float* WMg = (const float*)d_in[9];
    const float* bMg = (const float*)d_in[10];
    const float* WBg = (const float*)d_in[11];
    const float* bBg = (const float*)d_in[12];
    const float* Wup = (const float*)d_in[13];
    const float* Wdn = (const float*)d_in[14];
    const float* Wlf = (const float*)d_in[15];
    const float* Wrt = (const float*)d_in[16];
    float* outp = (float*)d_out;

    int nb = in_sizes[0] / (D * NV);
    size_t smem = SMEM_FLOATS * sizeof(float);
    cudaFuncSetAttribute(hgt_kernel, cudaFuncAttributeMaxDynamicSharedMemorySize, (int)smem);
    hgt_kernel<<<nb, NT, smem>>>(node, WWg, maskg, Rg, AMg, WKg, bKg, WQg, bQg,
                                 WMg, bMg, WBg, bBg, Wup, Wdn, Wlf, Wrt, outp, nb);
}

// round 15
// speedup vs baseline: 1.0808x; 1.0123x over previous
#include <cuda_runtime.h>
#include <math.h>

#define NT 512
#define D 128
#define H 4
#define DK 32
#define M 5
#define NN 15
#define NV 64
#define PSTR 18            // padded stride for P buffers (even -> u64 stores)
#define PMSZ (128 * PSTR)  // 2304 floats per type

// ---------------- shared memory layout (floats) ----------------
// sm[0..4800)     : sMask (persistent)
// sm[4800..9920)  : sWW   (persistent, padded (5,64,16))
// sm[9920..10048) : sPO offset table
// S = sm + 10048, extent 46336:
//  P0/P1: Xpad S[10240..18560) stride-65 ; NIM S[0..10240)
//  P2   : PK S[10240..21760), PQ S[21760..33280), PM S[33280..44800)
//         K -> S[0..8192), Q -> S[10240..18432), MSG -> S[21760..29952)
//  P3   : A/aw -> S[29952..46336)  (softmax fused into QK^T epilogue)
//  P4   : RES S[0..8192) (swizzled res2), Cpad S[8192..16512) stride-65,
//         Wmsg/ww S[16512..20608), sPart S[21760..23808) (over dead MSG h0);
//         MSG h1-3 + sA alive
//  P5   : NIM2 S[16512..26752), PB S[0..11520)  (Cpad consumed by nim first)
#define SMEM_FLOATS (10048 + 46336)

typedef unsigned long long u64;

static __device__ __forceinline__ u64 bc2(float v) {
    u64 r; asm("mov.b64 %0, {%1, %1};" : "=l"(r) : "f"(v)); return r;
}
static __device__ __forceinline__ void fma2(u64& d, u64 a, u64 b) {
    asm("fma.rn.f32x2 %0, %1, %2, %0;" : "+l"(d) : "l"(a), "l"(b));
}
static __device__ __forceinline__ u64 add2(u64 a, u64 b) {
    u64 r; asm("add.rn.f32x2 %0, %1, %2;" : "=l"(r) : "l"(a), "l"(b)); return r;
}
static __device__ __forceinline__ u64 mul2(u64 a, u64 b) {
    u64 r; asm("mul.rn.f32x2 %0, %1, %2;" : "=l"(r) : "l"(a), "l"(b)); return r;
}
static __device__ __forceinline__ void unpk(u64 v, float& lo, float& hi) {
    asm("mov.b64 {%0, %1}, %2;" : "=f"(lo), "=f"(hi) : "l"(v));
}
static __device__ __forceinline__ float hsum2(u64 v) {
    float lo, hi; unpk(v, lo, hi); return lo + hi;
}
static __device__ __forceinline__ float gelu_exact(float x) {
    return 0.5f * x * (1.f + erff(x * 0.70710678118654752f));
}

// NIM[m][dd][n0..+3] = sum_nn In[dd][nn] * WW[m][nn][n0..]; 8-row x 4-col tile
static __device__ __forceinline__ void nim_calc8(const float* __restrict__ sIn /*stride65*/,
                                                 const float* __restrict__ sWW,
                                                 float* __restrict__ sNIM, int tid) {
    for (int t = tid; t < 320; t += NT) {
        int m = t >> 6;
        int r = t & 63;
        int dd0 = (r >> 2) << 3;
        int n0 = (r & 3) << 2;
        const float* xb = sIn + dd0 * 65;
        const float* wb = sWW + m * 1024 + n0;
        u64 a[8][2];
#pragma unroll
        for (int i = 0; i < 8; i++) { a[i][0] = 0ull; a[i][1] = 0ull; }
#pragma unroll 4
        for (int nn = 0; nn < 64; nn++) {
            ulonglong2 w = *(const ulonglong2*)(wb + nn * 16);
#pragma unroll
            for (int i = 0; i < 8; i++) {
                u64 v = bc2(xb[i * 65 + nn]);
                fma2(a[i][0], v, w.x);
                fma2(a[i][1], v, w.y);
            }
        }
        float* o = sNIM + m * 2048 + dd0 * 16 + n0;
#pragma unroll
        for (int i = 0; i < 8; i++)
            *(ulonglong2*)(o + i * 16) = make_ulonglong2(a[i][0], a[i][1]);
    }
}

#define FMA4(acc, wb_)                       \
    fma2(acc[0], wb_, nv0.x); fma2(acc[1], wb_, nv0.y); \
    fma2(acc[2], wb_, nv1.x); fma2(acc[3], wb_, nv1.y);

// u64 stores (PSTR even -> 8B-aligned)
static __device__ __forceinline__ void store8(float* __restrict__ P, int o, const u64* acc, float bias) {
    u64 bb = bc2(bias);
#pragma unroll
    for (int p = 0; p < 4; p++)
        *(u64*)(P + o + 2 * p) = add2(acc[p], bb);
}

// Fused K/Q/M projection: 2-row tile (dd, dd+64), j-split 2, f32x2
static __device__ __forceinline__ void proj3(const float* __restrict__ WK, const float* __restrict__ bK,
                                             const float* __restrict__ WQ, const float* __restrict__ bQ,
                                             const float* __restrict__ WM, const float* __restrict__ bM,
                                             const float* __restrict__ sNIM,
                                             float* __restrict__ PK, float* __restrict__ PQ,
                                             float* __restrict__ PM, int tid) {
    for (int t = tid; t < 640; t += NT) {
        int pairidx = t >> 1;
        int j0 = (t & 1) << 3;
        int m = pairidx >> 6;
        int dd0 = pairidx & 63;
        const float* nb = sNIM + m * 2048 + j0;
        int ro0 = (m * 128 + dd0) * 128;
        int ro1 = ro0 + 64 * 128;
        u64 aK0[4], aK1[4], aQ0[4], aQ1[4], aM0[4], aM1[4];
#pragma unroll
        for (int j = 0; j < 4; j++) {
            aK0[j] = aK1[j] = aQ0[j] = aQ1[j] = aM0[j] = aM1[j] = 0ull;
        }
        for (int e4 = 0; e4 < 128; e4 += 4) {
            float4 wK0 = *(const float4*)(WK + ro0 + e4);
            float4 wK1 = *(const float4*)(WK + ro1 + e4);
            float4 wQ0 = *(const float4*)(WQ + ro0 + e4);
            float4 wQ1 = *(const float4*)(WQ + ro1 + e4);
            float4 wM0 = *(const float4*)(WM + ro0 + e4);
            float4 wM1 = *(const float4*)(WM + ro1 + e4);
#pragma unroll
            for (int u = 0; u < 4; u++) {
                ulonglong2 nv0 = *(const ulonglong2*)(nb + (e4 + u) * 16);
                ulonglong2 nv1 = *(const ulonglong2*)(nb + (e4 + u) * 16 + 4);
                u64 bk0 = bc2(((const float*)&wK0)[u]);
                u64 bk1 = bc2(((const float*)&wK1)[u]);
                u64 bq0 = bc2(((const float*)&wQ0)[u]);
                u64 bq1 = bc2(((const float*)&wQ1)[u]);
                u64 bm0 = bc2(((const float*)&wM0)[u]);
                u64 bm1 = bc2(((const float*)&wM1)[u]);
                FMA4(aK0, bk0) FMA4(aK1, bk1)
                FMA4(aQ0, bq0) FMA4(aQ1, bq1)
                FMA4(aM0, bm0) FMA4(aM1, bm1)
            }
        }
        int o0 = m * PMSZ + dd0 * PSTR + j0;
        int o1 = o0 + 64 * PSTR;
        store8(PK, o0, aK0, bK[m * 128 + dd0]);
        store8(PK, o1, aK1, bK[m * 128 + dd0 + 64]);
        store8(PQ, o0, aQ0, bQ[m * 128 + dd0]);
        store8(PQ, o1, aQ1, bQ[m * 128 + dd0 + 64]);
        store8(PM, o0, aM0, bM[m * 128 + dd0]);
        store8(PM, o1, aM1, bM[m * 128 + dd0 + 64]);
    }
}

// single projection (WB): 4-row tile, j-split 2, f32x2
static __device__ __forceinline__ void proj1(const float* __restrict__ W, const float* __restrict__ bg,
                                             const float* __restrict__ sNIM, float* __restrict__ P,
                                             int tid) {
    for (int t = tid; t < 320; t += NT) {
        int gidx = t >> 1;
        int j0 = (t & 1) << 3;
        int m = gidx >> 5;
        int dd0 = gidx & 31;
        const float* nb = sNIM + m * 2048 + j0;
        int ro[4];
#pragma unroll
        for (int i = 0; i < 4; i++) ro[i] = (m * 128 + dd0 + 32 * i) * 128;
        u64 a0[4], a1[4], a2[4], a3[4];
#pragma unroll
        for (int j = 0; j < 4; j++) { a0[j] = a1[j] = a2[j] = a3[j] = 0ull; }
        for (int e4 = 0; e4 < 128; e4 += 4) {
            float4 w0 = *(const float4*)(W + ro[0] + e4);
            float4 w1 = *(const float4*)(W + ro[1] + e4);
            float4 w2 = *(const float4*)(W + ro[2] + e4);
            float4 w3 = *(const float4*)(W + ro[3] + e4);
#pragma unroll
            for (int u = 0; u < 4; u++) {
                ulonglong2 nv0 = *(const ulonglong2*)(nb + (e4 + u) * 16);
                ulonglong2 nv1 = *(const ulonglong2*)(nb + (e4 + u) * 16 + 4);
                u64 b0 = bc2(((const float*)&w0)[u]);
                u64 b1 = bc2(((const float*)&w1)[u]);
                u64 b2 = bc2(((const float*)&w2)[u]);
                u64 b3 = bc2(((const float*)&w3)[u]);
                FMA4(a0, b0) FMA4(a1, b1) FMA4(a2, b2) FMA4(a3, b3)
            }
        }
#pragma unroll
        for (int i = 0; i < 4; i++) {
            const u64* acc = (i == 0) ? a0 : (i == 1) ? a1 : (i == 2) ? a2 : a3;
            int o = m * PMSZ + (dd0 + 32 * i) * PSTR + j0;
            store8(P, o, acc, bg[m * 128 + dd0 + 32 * i]);
        }
    }
}

// stage1: ww[ii][j] = aw[h][i0+ii][j%64] * AM[i0+ii][j], XOR-swizzled; 1024 items
static __device__ __forceinline__ void stage1_ww(const float* __restrict__ sA,
                                                 const float* __restrict__ AMg,
                                                 float* __restrict__ sWB4,
                                                 int h, int i0, int tid) {
#pragma unroll
    for (int rep = 0; rep < 2; rep++) {
        int idx = tid + rep * NT;
        int ii = idx >> 6;
        int j4 = (idx & 63) << 2;
        int i = i0 + ii;
        float4 am = *(const float4*)(AMg + i * 256 + j4);
        float4 av = *(const float4*)(sA + (h * 64 + i) * 64 + (j4 & 63));
        float4 w;
        w.x = av.x * am.x; w.y = av.y * am.y; w.z = av.z * am.z; w.w = av.w * am.w;
        *(float4*)(sWB4 + ii * 256 + (j4 ^ (ii << 2))) = w;
    }
}

// Wmsg load (head-independent), swizzled [q][(kk+q)&31]
static __device__ __forceinline__ void load_wmsg(float* __restrict__ sWB4,
                                                 const float* __restrict__ Wup,
                                                 const float* __restrict__ Wdn,
                                                 const float* __restrict__ Wlf,
                                                 const float* __restrict__ Wrt, int tid) {
#pragma unroll
    for (int rep = 0; rep < 8; rep++) {
        int i = tid + rep * NT;
        int q = i >> 5, kk = i & 31;
        int dir = q >> 5, col = q & 31;
        const float* Wd = (dir == 0) ? Wup : (dir == 1) ? Wdn : (dir == 2) ? Wlf : Wrt;
        sWB4[(q << 5) + ((kk + q) & 31)] = Wd[kk * 32 + col];
    }
}

__global__ void __launch_bounds__(NT, 1)
hgt_kernel(const float* __restrict__ node, const float* __restrict__ WWg,
           const float* __restrict__ maskg, const float* __restrict__ Rg,
           const float* __restrict__ AMg,
           const float* __restrict__ WKg, const float* __restrict__ bKg,
           const float* __restrict__ WQg, const float* __restrict__ bQg,
           const float* __restrict__ WMg, const float* __restrict__ bMg,
           const float* __restrict__ WBg, const float* __restrict__ bBg,
           const float* __restrict__ Wup, const float* __restrict__ Wdn,
           const float* __restrict__ Wlf, const float* __restrict__ Wrt,
           float* __restrict__ outp, int nb) {
    const int b = blockIdx.x;
    const int tid = threadIdx.x;
    const int BS = nb * NV;
    extern __shared__ float sm[];
    float* sMask = sm;
    float* sWW = sm + 4800;
    int* sPO = (int*)(sm + 9920);
    float* S = sm + 10048;

    // ---- P0: loads ----
    for (int i = tid; i < 4800; i += NT) sMask[i] = maskg[i];
    for (int i = tid; i < 4800; i += NT) {
        int m = i / 960;
        int r = i - m * 960;
        int nn = r / 15;
        int N = r - nn * 15;
        sWW[m * 1024 + nn * 16 + N] = WWg[b * 4800 + i];
    }
    for (int i = tid; i < 320; i += NT) sWW[i * 16 + 15] = 0.f;
    if (tid < 75) sPO[tid] = (tid / 15) * PMSZ + (tid % 15);
    {
        float* sX = S + 10240;
        for (int i = tid; i < 8192; i += NT) {
            int d = i >> 6, nn = i & 63;
            sX[d * 65 + nn] = node[d * BS + b * 64 + nn];
        }
    }
    __syncthreads();

    // ---- P1: NIM ----
    float* sNIM = S;
    nim_calc8(S + 10240, sWW, sNIM, tid);
    __syncthreads();

    // ---- P2: fused K/Q/M projection + FUSED 3-way mask matmul ----
    float* sPK = S + 10240;
    float* sPQ = S + 21760;
    float* sPM = S + 33280;
    float* sK = S;
    float* sQ = S + 10240;
    float* sMSG = S + 21760;

    proj3(WKg, bKg, WQg, bQg, WMg, bMg, sNIM, sPK, sPQ, sPM, tid);
    __syncthreads();
    // fused K+Q+M maskmul: one bm read feeds all three; Q and M stores deferred
    {
        int t = tid;
        int dg = t >> 4, n0 = (t & 15) << 2;
        u64 k0[2], k1[2], k2[2], k3[2];
        u64 q0[2], q1[2], q2[2], q3[2];
        u64 g0[2], g1[2], g2[2], g3[2];
        k0[0] = k0[1] = k1[0] = k1[1] = k2[0] = k2[1] = k3[0] = k3[1] = 0ull;
        q0[0] = q0[1] = q1[0] = q1[1] = q2[0] = q2[1] = q3[0] = q3[1] = 0ull;
        g0[0] = g0[1] = g1[0] = g1[1] = g2[0] = g2[1] = g3[0] = g3[1] = 0ull;
        int r0 = dg * PSTR, r1 = (dg + 32) * PSTR, r2 = (dg + 64) * PSTR, r3 = (dg + 96) * PSTR;
        int mC[4], ddC[4], NC[4];
#pragma unroll
        for (int i = 0; i < 4; i++) {
            int f = (dg + 32 * i) * 75;
            mC[i] = f / 1920;
            int r = f - mC[i] * 1920;
            ddC[i] = r / 15;
            NC[i] = r - ddC[i] * 15;
        }
        for (int j = 0; j < 75; j++) {
            int po = sPO[j];
            ulonglong2 bm = *(const ulonglong2*)(sMask + j * 64 + n0);
            u64 sk0 = bc2(sPK[r0 + po]);
            u64 sk1 = bc2(sPK[r1 + po]);
            u64 sk2 = bc2(sPK[r2 + po]);
            u64 sk3 = bc2(sPK[r3 + po]);
            fma2(k0[0], sk0, bm.x); fma2(k0[1], sk0, bm.y);
            fma2(k1[0], sk1, bm.x); fma2(k1[1], sk1, bm.y);
            fma2(k2[0], sk2, bm.x); fma2(k2[1], sk2, bm.y);
            fma2(k3[0], sk3, bm.x); fma2(k3[1], sk3, bm.y);
            u64 sq0 = bc2(sPQ[r0 + po]);
            u64 sq1 = bc2(sPQ[r1 + po]);
            u64 sq2 = bc2(sPQ[r2 + po]);
            u64 sq3 = bc2(sPQ[r3 + po]);
            fma2(q0[0], sq0, bm.x); fma2(q0[1], sq0, bm.y);
            fma2(q1[0], sq1, bm.x); fma2(q1[1], sq1, bm.y);
            fma2(q2[0], sq2, bm.x); fma2(q2[1], sq2, bm.y);
            fma2(q3[0], sq3, bm.x); fma2(q3[1], sq3, bm.y);
            u64 sm0 = bc2(sPM[mC[0] * PMSZ + ddC[0] * PSTR + NC[0]]);
            u64 sm1 = bc2(sPM[mC[1] * PMSZ + ddC[1] * PSTR + NC[1]]);
            u64 sm2 = bc2(sPM[mC[2] * PMSZ + ddC[2] * PSTR + NC[2]]);
            u64 sm3 = bc2(sPM[mC[3] * PMSZ + ddC[3] * PSTR + NC[3]]);
            fma2(g0[0], sm0, bm.x); fma2(g0[1], sm0, bm.y);
            fma2(g1[0], sm1, bm.x); fma2(g1[1], sm1, bm.y);
            fma2(g2[0], sm2, bm.x); fma2(g2[1], sm2, bm.y);
            fma2(g3[0], sm3, bm.x); fma2(g3[1], sm3, bm.y);
#pragma unroll
            for (int i = 0; i < 4; i++) {
                if (++NC[i] == 15) {
                    NC[i] = 0;
                    if (++ddC[i] == 128) { ddC[i] = 0; ++mC[i]; }
                }
            }
        }
        *(ulonglong2*)(sK + dg * 64 + n0) = make_ulonglong2(k0[0], k0[1]);
        *(ulonglong2*)(sK + (dg + 32) * 64 + n0) = make_ulonglong2(k1[0], k1[1]);
        *(ulonglong2*)(sK + (dg + 64) * 64 + n0) = make_ulonglong2(k2[0], k2[1]);
        *(ulonglong2*)(sK + (dg + 96) * 64 + n0) = make_ulonglong2(k3[0], k3[1]);
        __syncthreads();  // all PK/PQ/PM reads done; regions reusable
        *(ulonglong2*)(sQ + dg * 64 + n0) = make_ulonglong2(q0[0], q0[1]);
        *(ulonglong2*)(sQ + (dg + 32) * 64 + n0) = make_ulonglong2(q1[0], q1[1]);
        *(ulonglong2*)(sQ + (dg + 64) * 64 + n0) = make_ulonglong2(q2[0], q2[1]);
        *(ulonglong2*)(sQ + (dg + 96) * 64 + n0) = make_ulonglong2(q3[0], q3[1]);
        *(ulonglong2*)(sMSG + dg * 64 + n0) = make_ulonglong2(g0[0], g0[1]);
        *(ulonglong2*)(sMSG + (dg + 32) * 64 + n0) = make_ulonglong2(g1[0], g1[1]);
        *(ulonglong2*)(sMSG + (dg + 64) * 64 + n0) = make_ulonglong2(g2[0], g2[1]);
        *(ulonglong2*)(sMSG + (dg + 96) * 64 + n0) = make_ulonglong2(g3[0], g3[1]);
    }
    __syncthreads();

    // ---- P3: A = Q^T K / sqrt(dk) with FUSED R-add + softmax epilogue ----
    float* sA = S + 29952;
    {
        int t = tid;
        int h = t >> 7, rem = t & 127, i0r = rem >> 3, j0 = (rem & 7) << 3;
        u64 a[4][4];
#pragma unroll
        for (int c = 0; c < 4; c++)
#pragma unroll
            for (int j = 0; j < 4; j++) a[c][j] = 0ull;
        for (int k = 0; k < 32; k++) {
            const float* kr = sK + (h * 32 + k) * 64 + j0;
            const float* qr = sQ + (h * 32 + k) * 64;
            ulonglong2 nv0 = *(const ulonglong2*)(kr);
            ulonglong2 nv1 = *(const ulonglong2*)(kr + 4);
#pragma unroll
            for (int c = 0; c < 4; c++) {
                u64 qv = bc2(qr[i0r + 16 * c]);
                FMA4(a[c], qv)
            }
        }
        const float s = 0.17677669529663687f;  // 1/sqrt(32)
#pragma unroll
        for (int c = 0; c < 4; c++) {
            int i = i0r + 16 * c;
            const float* rr = Rg + b * 16384 + (h * 64 + i) * 64 + j0;
            float4 rv0 = *(const float4*)(rr);
            float4 rv1 = *(const float4*)(rr + 4);
            float v[8];
            {
                float lo, hi;
                unpk(a[c][0], lo, hi); v[0] = lo * s + rv0.x; v[1] = hi * s + rv0.y;
                unpk(a[c][1], lo, hi); v[2] = lo * s + rv0.z; v[3] = hi * s + rv0.w;
                unpk(a[c][2], lo, hi); v[4] = lo * s + rv1.x; v[5] = hi * s + rv1.y;
                unpk(a[c][3], lo, hi); v[6] = lo * s + rv1.z; v[7] = hi * s + rv1.w;
            }
            float mx = v[0];
#pragma unroll
            for (int j = 1; j < 8; j++) mx = fmaxf(mx, v[j]);
            mx = fmaxf(mx, __shfl_xor_sync(0xffffffffu, mx, 1));
            mx = fmaxf(mx, __shfl_xor_sync(0xffffffffu, mx, 2));
            mx = fmaxf(mx, __shfl_xor_sync(0xffffffffu, mx, 4));
            float sum = 0.f;
#pragma unroll
            for (int j = 0; j < 8; j++) { v[j] = __expf(v[j] - mx); sum += v[j]; }
            sum += __shfl_xor_sync(0xffffffffu, sum, 1);
            sum += __shfl_xor_sync(0xffffffffu, sum, 2);
            sum += __shfl_xor_sync(0xffffffffu, sum, 4);
            float inv = 1.f / sum;
            float4 o0, o1;
            o0.x = v[0] * inv; o0.y = v[1] * inv; o0.z = v[2] * inv; o0.w = v[3] * inv;
            o1.x = v[4] * inv; o1.y = v[5] * inv; o1.z = v[6] * inv; o1.w = v[7] * inv;
            float* op = sA + (h * 64 + i) * 64 + j0;
            *(float4*)(op) = o0;
            *(float4*)(op + 4) = o1;
        }
    }
    __syncthreads();

    // ---- P4 buffers ----
    float* sRES = S;            // swizzled res2 [32][256]
    float* sCpad = S + 8192;    // stride-65 gelu output
    float* sWB4 = S + 16512;    // Wmsg / ww tile
    float* sPart = S + 21760;   // 2048 split-K partials (over dead MSG head-0)

    // aw[0,0] output (b==0) fused with head-0 Wmsg load
    if (b == 0) {
        for (int idx = tid; idx < 4096; idx += NT) {
            int ii = idx >> 6, j4 = (idx & 63) << 2;
            float4 am = *(const float4*)(AMg + ii * 256 + j4);
            float4 av = *(const float4*)(sA + ii * 64 + (j4 & 63));
            float4 o;
            o.x = av.x * am.x; o.y = av.y * am.y; o.z = av.z * am.z; o.w = av.w * am.w;
            *(float4*)(outp + D * BS + ii * 256 + j4) = o;
        }
    }
    load_wmsg(sWB4, Wup, Wdn, Wlf, Wrt, tid);
    __syncthreads();

    // ---- P4: per-head res + masked attention apply + gelu -> Cpad ----
    for (int h = 0; h < 4; h++) {
        // RES (512 threads, 4q x 4n) -> swizzled res2
        {
            int qg = tid >> 4;
            int n0 = (tid & 15) << 2;
            u64 c[4][2];
#pragma unroll
            for (int s = 0; s < 4; s++) { c[s][0] = 0ull; c[s][1] = 0ull; }
            for (int kk = 0; kk < 32; kk++) {
                const float* mr = sMSG + (h * 32 + kk) * 64 + n0;
                ulonglong2 nv = *(const ulonglong2*)(mr);
#pragma unroll
                for (int s = 0; s < 4; s++) {
                    int q = qg + 32 * s;
                    u64 w = bc2(sWB4[(q << 5) + ((kk + q) & 31)]);
                    fma2(c[s][0], w, nv.x);
                    fma2(c[s][1], w, nv.y);
                }
            }
#pragma unroll
            for (int s = 0; s < 4; s++) {
                int q = qg + 32 * s;
                int kq = q >> 2;
                int off = ((q & 3) << 6) + n0;
                int sw = (kq & 7) << 2;
                *(ulonglong2*)(sRES + (kq << 8) + (off ^ sw)) =
                    make_ulonglong2(c[s][0], c[s][1]);
            }
        }
        __syncthreads();  // RES done; sWB4 (Wmsg) free to become ww
        stage1_ww(sA, AMg, sWB4, h, 0, tid);
        __syncthreads();

        for (int i0 = 0; i0 < 64; i0 += 16) {
            // stage2: 4-way split-K x 2 ii-halves across 8 warps, 4k x 2ii tiles
            if (tid < 256) {
                int warp = tid >> 5;
                int g = warp & 3;        // j2 quarter
                int half = warp >> 2;    // ii half
                int r = tid & 31;
                int kp = r >> 2;         // 0..7
                int iip = r & 3;         // 0..3
                int jbase = g << 6;
                int ksw = kp << 2;
                int iiA = half * 8 + iip;
                int iiB = iiA + 4;
                const float* wA = sWB4 + (iiA << 8);
                const float* wB = sWB4 + (iiB << 8);
                int swA = iiA << 2, swB = iiB << 2;
                u64 acc[4][2];
#pragma unroll
                for (int c = 0; c < 4; c++) { acc[c][0] = 0ull; acc[c][1] = 0ull; }
#pragma unroll 4
                for (int jj = 0; jj < 64; jj += 4) {
                    int j2 = jbase + jj;
                    int jx = j2 ^ ksw;
                    ulonglong2 rv[4];
#pragma unroll
                    for (int c = 0; c < 4; c++)
                        rv[c] = *(const ulonglong2*)(sRES + ((kp + 8 * c) << 8) + jx);
                    ulonglong2 wvA = *(const ulonglong2*)(wA + (j2 ^ swA));
                    ulonglong2 wvB = *(const ulonglong2*)(wB + (j2 ^ swB));
#pragma unroll
                    for (int c = 0; c < 4; c++) {
                        fma2(acc[c][0], rv[c].x, wvA.x);
                        fma2(acc[c][0], rv[c].y, wvA.y);
                        fma2(acc[c][1], rv[c].x, wvB.x);
                        fma2(acc[c][1], rv[c].y, wvB.y);
                    }
                }
                int gb = g << 9;
#pragma unroll
                for (int c = 0; c < 4; c++) {
                    int k = kp + 8 * c;
                    sPart[gb + (k << 4) + iiA] = hsum2(acc[c][0]);
                    sPart[gb + (k << 4) + iiB] = hsum2(acc[c][1]);
                }
            }
            __syncthreads();
            // stage3: reduce + gelu -> Cpad ; fused with stage1(next) or Wmsg(next head)
            {
                float v = sPart[tid] + sPart[512 + tid] + sPart[1024 + tid] + sPart[1536 + tid];
                int k = tid >> 4, ii = tid & 15;
                sCpad[(h * 32 + k) * 65 + i0 + ii] = gelu_exact(v);
            }
            if (i0 < 48) {
                stage1_ww(sA, AMg, sWB4, h, i0 + 16, tid);
            } else if (h < 3) {
                load_wmsg(sWB4, Wup, Wdn, Wlf, Wrt, tid);
            }
            __syncthreads();
        }
    }

    // ---- P5: back-projection + residual (Cpad already stride-65) ----
    float* sNIM2 = S + 16512;
    nim_calc8(sCpad, sWW, sNIM2, tid);
    __syncthreads();
    float* sPB = S;
    proj1(WBg, bBg, sNIM2, sPB, tid);
    __syncthreads();

    for (int t = tid; t < 512; t += NT) {
        int dg = t >> 4, n0 = (t & 15) << 2;
        u64 a0[2], a1[2], a2[2], a3[2];
        a0[0] = a0[1] = a1[0] = a1[1] = a2[0] = a2[1] = a3[0] = a3[1] = 0ull;
        const float* p0 = sPB + dg * PSTR;
        const float* p1 = sPB + (dg + 32) * PSTR;
        const float* p2 = sPB + (dg + 64) * PSTR;
        const float* p3 = sPB + (dg + 96) * PSTR;
        for (int j = 0; j < 75; j++) {
            int po = sPO[j];
            u64 s0 = bc2(p0[po]);
            u64 s1 = bc2(p1[po]);
            u64 s2 = bc2(p2[po]);
            u64 s3 = bc2(p3[po]);
            ulonglong2 bm = *(const ulonglong2*)(sMask + j * 64 + n0);
            fma2(a0[0], s0, bm.x); fma2(a0[1], s0, bm.y);
            fma2(a1[0], s1, bm.x); fma2(a1[1], s1, bm.y);
            fma2(a2[0], s2, bm.x); fma2(a2[1], s2, bm.y);
            fma2(a3[0], s3, bm.x); fma2(a3[1], s3, bm.y);
        }
#pragma unroll
        for (int i = 0; i < 4; i++) {
            const u64* acc = (i == 0) ? a0 : (i == 1) ? a1 : (i == 2) ? a2 : a3;
            int d = dg + 32 * i;
            int gi = d * BS + b * 64 + n0;
            ulonglong2 rr = *(const ulonglong2*)(node + gi);
            *(ulonglong2*)(outp + gi) =
                make_ulonglong2(add2(acc[0], rr.x), add2(acc[1], rr.y));
        }
    }
}

extern "C" void kernel_launch(void* const* d_in, const int* in_sizes, int n_in,
                              void* d_out, int out_size) {
    const float* node = (const float*)d_in[0];
    const float* WWg = (const float*)d_in[1];
    const float* maskg = (const float*)d_in[2];
    const float* Rg = (const float*)d_in[3];
    const float* AMg = (const float*)d_in[4];
    const float* WKg = (const float*)d_in[5];
    const float* bKg = (const float*)d_in[6];
    const float* WQg = (const float*)d_in[7];
    const float* bQg = (const float*)d_in[8];
    const float* WMg = (const float*)d_in[9];
    const float* bMg = (const float*)d_in[10];
    const float* WBg = (const float*)d_in[11];
    const float* bBg = (const float*)d_in[12];
    const float* Wup = (const float*)d_in[13];
    const float* Wdn = (const float*)d_in[14];
    const float* Wlf = (const float*)d_in[15];
    const float* Wrt = (const float*)d_in[16];
    float* outp = (float*)d_out;

    int nb = in_sizes[0] / (D * NV);
    size_t smem = SMEM_FLOATS * sizeof(float);
    cudaFuncSetAttribute(hgt_kernel, cudaFuncAttributeMaxDynamicSharedMemorySize, (int)smem);
    hgt_kernel<<<nb, NT, smem>>>(node, WWg, maskg, Rg, AMg, WKg, bKg, WQg, bQg,
                                 WMg, bMg, WBg, bBg, Wup, Wdn, Wlf, Wrt, outp, nb);
}

// round 16
// speedup vs baseline: 1.1048x; 1.0222x over previous
#include <cuda_runtime.h>
#include <math.h>

#define NT 512
#define D 128
#define H 4
#define DK 32
#define M 5
#define NN 15
#define NV 64
#define PSTR 18            // padded stride for P buffers (even -> u64 stores)
#define PMSZ (128 * PSTR)  // 2304 floats per type (== 128*PSTR, wrap-free cursors)

// ---------------- shared memory layout (floats) ----------------
// sm[0..4800)     : sMask (persistent)
// sm[4800..9920)  : sWW   (persistent, padded (5,64,16))
// sm[9920..10048) : sPO offset table
// S = sm + 10048, extent 46336:
//  P0/P1: Xpad S[10240..18560) stride-65 ; NIM S[0..10240)
//  P2   : PK S[10240..21760), PQ S[21760..33280), PM S[33280..44800)
//         K -> S[0..8192), Q -> S[10240..18432), MSG -> S[21760..29952)
//  P3   : A/aw -> S[29952..46336)  (softmax fused into QK^T epilogue)
//  P4   : RES S[0..8192) (swizzled res2), Cpad S[8192..16512) stride-65,
//         Wmsg/ww S[16512..20608), sPart S[21760..23808) (over dead MSG h0);
//         MSG h1-3 + sA alive
//  P5   : NIM2 S[16512..26752), PB S[0..11520)  (Cpad consumed by nim first)
#define SMEM_FLOATS (10048 + 46336)

typedef unsigned long long u64;

static __device__ __forceinline__ u64 bc2(float v) {
    u64 r; asm("mov.b64 %0, {%1, %1};" : "=l"(r) : "f"(v)); return r;
}
static __device__ __forceinline__ void fma2(u64& d, u64 a, u64 b) {
    asm("fma.rn.f32x2 %0, %1, %2, %0;" : "+l"(d) : "l"(a), "l"(b));
}
static __device__ __forceinline__ u64 add2(u64 a, u64 b) {
    u64 r; asm("add.rn.f32x2 %0, %1, %2;" : "=l"(r) : "l"(a), "l"(b)); return r;
}
static __device__ __forceinline__ u64 mul2(u64 a, u64 b) {
    u64 r; asm("mul.rn.f32x2 %0, %1, %2;" : "=l"(r) : "l"(a), "l"(b)); return r;
}
static __device__ __forceinline__ void unpk(u64 v, float& lo, float& hi) {
    asm("mov.b64 {%0, %1}, %2;" : "=f"(lo), "=f"(hi) : "l"(v));
}
static __device__ __forceinline__ float hsum2(u64 v) {
    float lo, hi; unpk(v, lo, hi); return lo + hi;
}
static __device__ __forceinline__ float gelu_exact(float x) {
    return 0.5f * x * (1.f + erff(x * 0.70710678118654752f));
}

// NIM[m][dd][n0..+3] = sum_nn In[dd][nn] * WW[m][nn][n0..]; 8-row x 4-col tile
static __device__ __forceinline__ void nim_calc8(const float* __restrict__ sIn /*stride65*/,
                                                 const float* __restrict__ sWW,
                                                 float* __restrict__ sNIM, int tid) {
    for (int t = tid; t < 320; t += NT) {
        int m = t >> 6;
        int r = t & 63;
        int dd0 = (r >> 2) << 3;
        int n0 = (r & 3) << 2;
        const float* xb = sIn + dd0 * 65;
        const float* wb = sWW + m * 1024 + n0;
        u64 a[8][2];
#pragma unroll
        for (int i = 0; i < 8; i++) { a[i][0] = 0ull; a[i][1] = 0ull; }
#pragma unroll 4
        for (int nn = 0; nn < 64; nn++) {
            ulonglong2 w = *(const ulonglong2*)(wb + nn * 16);
#pragma unroll
            for (int i = 0; i < 8; i++) {
                u64 v = bc2(xb[i * 65 + nn]);
                fma2(a[i][0], v, w.x);
                fma2(a[i][1], v, w.y);
            }
        }
        float* o = sNIM + m * 2048 + dd0 * 16 + n0;
#pragma unroll
        for (int i = 0; i < 8; i++)
            *(ulonglong2*)(o + i * 16) = make_ulonglong2(a[i][0], a[i][1]);
    }
}

#define FMA4(acc, wb_)                       \
    fma2(acc[0], wb_, nv0.x); fma2(acc[1], wb_, nv0.y); \
    fma2(acc[2], wb_, nv1.x); fma2(acc[3], wb_, nv1.y);

// u64 stores (PSTR even -> 8B-aligned)
static __device__ __forceinline__ void store8(float* __restrict__ P, int o, const u64* acc, float bias) {
    u64 bb = bc2(bias);
#pragma unroll
    for (int p = 0; p < 4; p++)
        *(u64*)(P + o + 2 * p) = add2(acc[p], bb);
}

// Fused K/Q/M projection: 2-row tile (dd, dd+64), j-split 2, f32x2
static __device__ __forceinline__ void proj3(const float* __restrict__ WK, const float* __restrict__ bK,
                                             const float* __restrict__ WQ, const float* __restrict__ bQ,
                                             const float* __restrict__ WM, const float* __restrict__ bM,
                                             const float* __restrict__ sNIM,
                                             float* __restrict__ PK, float* __restrict__ PQ,
                                             float* __restrict__ PM, int tid) {
    for (int t = tid; t < 640; t += NT) {
        int pairidx = t >> 1;
        int j0 = (t & 1) << 3;
        int m = pairidx >> 6;
        int dd0 = pairidx & 63;
        const float* nb = sNIM + m * 2048 + j0;
        int ro0 = (m * 128 + dd0) * 128;
        int ro1 = ro0 + 64 * 128;
        u64 aK0[4], aK1[4], aQ0[4], aQ1[4], aM0[4], aM1[4];
#pragma unroll
        for (int j = 0; j < 4; j++) {
            aK0[j] = aK1[j] = aQ0[j] = aQ1[j] = aM0[j] = aM1[j] = 0ull;
        }
        for (int e4 = 0; e4 < 128; e4 += 4) {
            float4 wK0 = *(const float4*)(WK + ro0 + e4);
            float4 wK1 = *(const float4*)(WK + ro1 + e4);
            float4 wQ0 = *(const float4*)(WQ + ro0 + e4);
            float4 wQ1 = *(const float4*)(WQ + ro1 + e4);
            float4 wM0 = *(const float4*)(WM + ro0 + e4);
            float4 wM1 = *(const float4*)(WM + ro1 + e4);
#pragma unroll
            for (int u = 0; u < 4; u++) {
                ulonglong2 nv0 = *(const ulonglong2*)(nb + (e4 + u) * 16);
                ulonglong2 nv1 = *(const ulonglong2*)(nb + (e4 + u) * 16 + 4);
                u64 bk0 = bc2(((const float*)&wK0)[u]);
                u64 bk1 = bc2(((const float*)&wK1)[u]);
                u64 bq0 = bc2(((const float*)&wQ0)[u]);
                u64 bq1 = bc2(((const float*)&wQ1)[u]);
                u64 bm0 = bc2(((const float*)&wM0)[u]);
                u64 bm1 = bc2(((const float*)&wM1)[u]);
                FMA4(aK0, bk0) FMA4(aK1, bk1)
                FMA4(aQ0, bq0) FMA4(aQ1, bq1)
                FMA4(aM0, bm0) FMA4(aM1, bm1)
            }
        }
        int o0 = m * PMSZ + dd0 * PSTR + j0;
        int o1 = o0 + 64 * PSTR;
        store8(PK, o0, aK0, bK[m * 128 + dd0]);
        store8(PK, o1, aK1, bK[m * 128 + dd0 + 64]);
        store8(PQ, o0, aQ0, bQ[m * 128 + dd0]);
        store8(PQ, o1, aQ1, bQ[m * 128 + dd0 + 64]);
        store8(PM, o0, aM0, bM[m * 128 + dd0]);
        store8(PM, o1, aM1, bM[m * 128 + dd0 + 64]);
    }
}

// single projection (WB): 4-row tile, j-split 2, f32x2
static __device__ __forceinline__ void proj1(const float* __restrict__ W, const float* __restrict__ bg,
                                             const float* __restrict__ sNIM, float* __restrict__ P,
                                             int tid) {
    for (int t = tid; t < 320; t += NT) {
        int gidx = t >> 1;
        int j0 = (t & 1) << 3;
        int m = gidx >> 5;
        int dd0 = gidx & 31;
        const float* nb = sNIM + m * 2048 + j0;
        int ro[4];
#pragma unroll
        for (int i = 0; i < 4; i++) ro[i] = (m * 128 + dd0 + 32 * i) * 128;
        u64 a0[4], a1[4], a2[4], a3[4];
#pragma unroll
        for (int j = 0; j < 4; j++) { a0[j] = a1[j] = a2[j] = a3[j] = 0ull; }
        for (int e4 = 0; e4 < 128; e4 += 4) {
            float4 w0 = *(const float4*)(W + ro[0] + e4);
            float4 w1 = *(const float4*)(W + ro[1] + e4);
            float4 w2 = *(const float4*)(W + ro[2] + e4);
            float4 w3 = *(const float4*)(W + ro[3] + e4);
#pragma unroll
            for (int u = 0; u < 4; u++) {
                ulonglong2 nv0 = *(const ulonglong2*)(nb + (e4 + u) * 16);
                ulonglong2 nv1 = *(const ulonglong2*)(nb + (e4 + u) * 16 + 4);
                u64 b0 = bc2(((const float*)&w0)[u]);
                u64 b1 = bc2(((const float*)&w1)[u]);
                u64 b2 = bc2(((const float*)&w2)[u]);
                u64 b3 = bc2(((const float*)&w3)[u]);
                FMA4(a0, b0) FMA4(a1, b1) FMA4(a2, b2) FMA4(a3, b3)
            }
        }
#pragma unroll
        for (int i = 0; i < 4; i++) {
            const u64* acc = (i == 0) ? a0 : (i == 1) ? a1 : (i == 2) ? a2 : a3;
            int o = m * PMSZ + (dd0 + 32 * i) * PSTR + j0;
            store8(P, o, acc, bg[m * 128 + dd0 + 32 * i]);
        }
    }
}

// stage1: ww[ii][j] = aw[h][i0+ii][j%64] * AM[i0+ii][j], XOR-swizzled; 1024 items
static __device__ __forceinline__ void stage1_ww(const float* __restrict__ sA,
                                                 const float* __restrict__ AMg,
                                                 float* __restrict__ sWB4,
                                                 int h, int i0, int tid) {
#pragma unroll
    for (int rep = 0; rep < 2; rep++) {
        int idx = tid + rep * NT;
        int ii = idx >> 6;
        int j4 = (idx & 63) << 2;
        int i = i0 + ii;
        float4 am = *(const float4*)(AMg + i * 256 + j4);
        float4 av = *(const float4*)(sA + (h * 64 + i) * 64 + (j4 & 63));
        float4 w;
        w.x = av.x * am.x; w.y = av.y * am.y; w.z = av.z * am.z; w.w = av.w * am.w;
        *(float4*)(sWB4 + ii * 256 + (j4 ^ (ii << 2))) = w;
    }
}

// Wmsg load (head-independent), swizzled [q][(kk+q)&31]
static __device__ __forceinline__ void load_wmsg(float* __restrict__ sWB4,
                                                 const float* __restrict__ Wup,
                                                 const float* __restrict__ Wdn,
                                                 const float* __restrict__ Wlf,
                                                 const float* __restrict__ Wrt, int tid) {
#pragma unroll
    for (int rep = 0; rep < 8; rep++) {
        int i = tid + rep * NT;
        int q = i >> 5, kk = i & 31;
        int dir = q >> 5, col = q & 31;
        const float* Wd = (dir == 0) ? Wup : (dir == 1) ? Wdn : (dir == 2) ? Wlf : Wrt;
        sWB4[(q << 5) + ((kk + q) & 31)] = Wd[kk * 32 + col];
    }
}

__global__ void __launch_bounds__(NT, 1)
hgt_kernel(const float* __restrict__ node, const float* __restrict__ WWg,
           const float* __restrict__ maskg, const float* __restrict__ Rg,
           const float* __restrict__ AMg,
           const float* __restrict__ WKg, const float* __restrict__ bKg,
           const float* __restrict__ WQg, const float* __restrict__ bQg,
           const float* __restrict__ WMg, const float* __restrict__ bMg,
           const float* __restrict__ WBg, const float* __restrict__ bBg,
           const float* __restrict__ Wup, const float* __restrict__ Wdn,
           const float* __restrict__ Wlf, const float* __restrict__ Wrt,
           float* __restrict__ outp, int nb) {
    const int b = blockIdx.x;
    const int tid = threadIdx.x;
    const int BS = nb * NV;
    extern __shared__ float sm[];
    float* sMask = sm;
    float* sWW = sm + 4800;
    int* sPO = (int*)(sm + 9920);
    float* S = sm + 10048;

    // ---- P0: loads ----
    for (int i = tid; i < 4800; i += NT) sMask[i] = maskg[i];
    for (int i = tid; i < 4800; i += NT) {
        int m = i / 960;
        int r = i - m * 960;
        int nn = r / 15;
        int N = r - nn * 15;
        sWW[m * 1024 + nn * 16 + N] = WWg[b * 4800 + i];
    }
    for (int i = tid; i < 320; i += NT) sWW[i * 16 + 15] = 0.f;
    if (tid < 75) sPO[tid] = (tid / 15) * PMSZ + (tid % 15);
    {
        float* sX = S + 10240;
        for (int i = tid; i < 8192; i += NT) {
            int d = i >> 6, nn = i & 63;
            sX[d * 65 + nn] = node[d * BS + b * 64 + nn];
        }
    }
    __syncthreads();

    // ---- P1: NIM ----
    float* sNIM = S;
    nim_calc8(S + 10240, sWW, sNIM, tid);
    __syncthreads();

    // ---- P2: fused K/Q/M projection + FUSED 3-way mask matmul ----
    float* sPK = S + 10240;
    float* sPQ = S + 21760;
    float* sPM = S + 33280;
    float* sK = S;
    float* sQ = S + 10240;
    float* sMSG = S + 21760;

    proj3(WKg, bKg, WQg, bQg, WMg, bMg, sNIM, sPK, sPQ, sPM, tid);
    __syncthreads();
    // fused K+Q+M maskmul: one bm read feeds all three; Q and M stores deferred.
    // msg cursors simplified: PMSZ == 128*PSTR makes the dd->m wrap offset-free,
    // so each cursor is just (off, N).
    {
        int t = tid;
        int dg = t >> 4, n0 = (t & 15) << 2;
        u64 k0[2], k1[2], k2[2], k3[2];
        u64 q0[2], q1[2], q2[2], q3[2];
        u64 g0[2], g1[2], g2[2], g3[2];
        k0[0] = k0[1] = k1[0] = k1[1] = k2[0] = k2[1] = k3[0] = k3[1] = 0ull;
        q0[0] = q0[1] = q1[0] = q1[1] = q2[0] = q2[1] = q3[0] = q3[1] = 0ull;
        g0[0] = g0[1] = g1[0] = g1[1] = g2[0] = g2[1] = g3[0] = g3[1] = 0ull;
        int r0 = dg * PSTR, r1 = (dg + 32) * PSTR, r2 = (dg + 64) * PSTR, r3 = (dg + 96) * PSTR;
        int off[4], NC[4];
#pragma unroll
        for (int i = 0; i < 4; i++) {
            int f = (dg + 32 * i) * 75;
            int m = f / 1920;
            int r = f - m * 1920;
            int dd = r / 15;
            NC[i] = r - dd * 15;
            off[i] = m * PMSZ + dd * PSTR + NC[i];
        }
        for (int j = 0; j < 75; j++) {
            int po = sPO[j];
            ulonglong2 bm = *(const ulonglong2*)(sMask + j * 64 + n0);
            u64 sk0 = bc2(sPK[r0 + po]);
            u64 sk1 = bc2(sPK[r1 + po]);
            u64 sk2 = bc2(sPK[r2 + po]);
            u64 sk3 = bc2(sPK[r3 + po]);
            fma2(k0[0], sk0, bm.x); fma2(k0[1], sk0, bm.y);
            fma2(k1[0], sk1, bm.x); fma2(k1[1], sk1, bm.y);
            fma2(k2[0], sk2, bm.x); fma2(k2[1], sk2, bm.y);
            fma2(k3[0], sk3, bm.x); fma2(k3[1], sk3, bm.y);
            u64 sq0 = bc2(sPQ[r0 + po]);
            u64 sq1 = bc2(sPQ[r1 + po]);
            u64 sq2 = bc2(sPQ[r2 + po]);
            u64 sq3 = bc2(sPQ[r3 + po]);
            fma2(q0[0], sq0, bm.x); fma2(q0[1], sq0, bm.y);
            fma2(q1[0], sq1, bm.x); fma2(q1[1], sq1, bm.y);
            fma2(q2[0], sq2, bm.x); fma2(q2[1], sq2, bm.y);
            fma2(q3[0], sq3, bm.x); fma2(q3[1], sq3, bm.y);
            u64 sm0 = bc2(sPM[off[0]]);
            u64 sm1 = bc2(sPM[off[1]]);
            u64 sm2 = bc2(sPM[off[2]]);
            u64 sm3 = bc2(sPM[off[3]]);
            fma2(g0[0], sm0, bm.x); fma2(g0[1], sm0, bm.y);
            fma2(g1[0], sm1, bm.x); fma2(g1[1], sm1, bm.y);
            fma2(g2[0], sm2, bm.x); fma2(g2[1], sm2, bm.y);
            fma2(g3[0], sm3, bm.x); fma2(g3[1], sm3, bm.y);
#pragma unroll
            for (int i = 0; i < 4; i++) {
                off[i]++;
                if (++NC[i] == 15) { NC[i] = 0; off[i] += PSTR - 15; }
            }
        }
        *(ulonglong2*)(sK + dg * 64 + n0) = make_ulonglong2(k0[0], k0[1]);
        *(ulonglong2*)(sK + (dg + 32) * 64 + n0) = make_ulonglong2(k1[0], k1[1]);
        *(ulonglong2*)(sK + (dg + 64) * 64 + n0) = make_ulonglong2(k2[0], k2[1]);
        *(ulonglong2*)(sK + (dg + 96) * 64 + n0) = make_ulonglong2(k3[0], k3[1]);
        __syncthreads();  // all PK/PQ/PM reads done; regions reusable
        *(ulonglong2*)(sQ + dg * 64 + n0) = make_ulonglong2(q0[0], q0[1]);
        *(ulonglong2*)(sQ + (dg + 32) * 64 + n0) = make_ulonglong2(q1[0], q1[1]);
        *(ulonglong2*)(sQ + (dg + 64) * 64 + n0) = make_ulonglong2(q2[0], q2[1]);
        *(ulonglong2*)(sQ + (dg + 96) * 64 + n0) = make_ulonglong2(q3[0], q3[1]);
        *(ulonglong2*)(sMSG + dg * 64 + n0) = make_ulonglong2(g0[0], g0[1]);
        *(ulonglong2*)(sMSG + (dg + 32) * 64 + n0) = make_ulonglong2(g1[0], g1[1]);
        *(ulonglong2*)(sMSG + (dg + 64) * 64 + n0) = make_ulonglong2(g2[0], g2[1]);
        *(ulonglong2*)(sMSG + (dg + 96) * 64 + n0) = make_ulonglong2(g3[0], g3[1]);
    }
    __syncthreads();

    // ---- P3: A = Q^T K / sqrt(dk) with FUSED R-add + softmax epilogue ----
    float* sA = S + 29952;
    {
        int t = tid;
        int h = t >> 7, rem = t & 127, i0r = rem >> 3, j0 = (rem & 7) << 3;
        u64 a[4][4];
#pragma unroll
        for (int c = 0; c < 4; c++)
#pragma unroll
            for (int j = 0; j < 4; j++) a[c][j] = 0ull;
        for (int k = 0; k < 32; k++) {
            const float* kr = sK + (h * 32 + k) * 64 + j0;
            const float* qr = sQ + (h * 32 + k) * 64;
            ulonglong2 nv0 = *(const ulonglong2*)(kr);
            ulonglong2 nv1 = *(const ulonglong2*)(kr + 4);
#pragma unroll
            for (int c = 0; c < 4; c++) {
                u64 qv = bc2(qr[i0r + 16 * c]);
                FMA4(a[c], qv)
            }
        }
        const float s = 0.17677669529663687f;  // 1/sqrt(32)
#pragma unroll
        for (int c = 0; c < 4; c++) {
            int i = i0r + 16 * c;
            const float* rr = Rg + b * 16384 + (h * 64 + i) * 64 + j0;
            float4 rv0 = *(const float4*)(rr);
            float4 rv1 = *(const float4*)(rr + 4);
            float v[8];
            {
                float lo, hi;
                unpk(a[c][0], lo, hi); v[0] = lo * s + rv0.x; v[1] = hi * s + rv0.y;
                unpk(a[c][1], lo, hi); v[2] = lo * s + rv0.z; v[3] = hi * s + rv0.w;
                unpk(a[c][2], lo, hi); v[4] = lo * s + rv1.x; v[5] = hi * s + rv1.y;
                unpk(a[c][3], lo, hi); v[6] = lo * s + rv1.z; v[7] = hi * s + rv1.w;
            }
            float mx = v[0];
#pragma unroll
            for (int j = 1; j < 8; j++) mx = fmaxf(mx, v[j]);
            mx = fmaxf(mx, __shfl_xor_sync(0xffffffffu, mx, 1));
            mx = fmaxf(mx, __shfl_xor_sync(0xffffffffu, mx, 2));
            mx = fmaxf(mx, __shfl_xor_sync(0xffffffffu, mx, 4));
            float sum = 0.f;
#pragma unroll
            for (int j = 0; j < 8; j++) { v[j] = __expf(v[j] - mx); sum += v[j]; }
            sum += __shfl_xor_sync(0xffffffffu, sum, 1);
            sum += __shfl_xor_sync(0xffffffffu, sum, 2);
            sum += __shfl_xor_sync(0xffffffffu, sum, 4);
            float inv = 1.f / sum;
            float4 o0, o1;
            o0.x = v[0] * inv; o0.y = v[1] * inv; o0.z = v[2] * inv; o0.w = v[3] * inv;
            o1.x = v[4] * inv; o1.y = v[5] * inv; o1.z = v[6] * inv; o1.w = v[7] * inv;
            float* op = sA + (h * 64 + i) * 64 + j0;
            *(float4*)(op) = o0;
            *(float4*)(op + 4) = o1;
        }
    }
    __syncthreads();

    // ---- P4 buffers ----
    float* sRES = S;            // swizzled res2 [32][256]
    float* sCpad = S + 8192;    // stride-65 gelu output
    float* sWB4 = S + 16512;    // Wmsg / ww tile
    float* sPart = S + 21760;   // 2048 split-K partials (over dead MSG head-0)

    // aw[0,0] output (b==0) fused with head-0 Wmsg load
    if (b == 0) {
        for (int idx = tid; idx < 4096; idx += NT) {
            int ii = idx >> 6, j4 = (idx & 63) << 2;
            float4 am = *(const float4*)(AMg + ii * 256 + j4);
            float4 av = *(const float4*)(sA + ii * 64 + (j4 & 63));
            float4 o;
            o.x = av.x * am.x; o.y = av.y * am.y; o.z = av.z * am.z; o.w = av.w * am.w;
            *(float4*)(outp + D * BS + ii * 256 + j4) = o;
        }
    }
    load_wmsg(sWB4, Wup, Wdn, Wlf, Wrt, tid);
    __syncthreads();

    // ---- P4: per-head res + masked attention apply + gelu -> Cpad ----
    for (int h = 0; h < 4; h++) {
        // RES (512 threads, 4q x 4n) -> swizzled res2
        {
            int qg = tid >> 4;
            int n0 = (tid & 15) << 2;
            u64 c[4][2];
#pragma unroll
            for (int s = 0; s < 4; s++) { c[s][0] = 0ull; c[s][1] = 0ull; }
            for (int kk = 0; kk < 32; kk++) {
                const float* mr = sMSG + (h * 32 + kk) * 64 + n0;
                ulonglong2 nv = *(const ulonglong2*)(mr);
#pragma unroll
                for (int s = 0; s < 4; s++) {
                    int q = qg + 32 * s;
                    u64 w = bc2(sWB4[(q << 5) + ((kk + q) & 31)]);
                    fma2(c[s][0], w, nv.x);
                    fma2(c[s][1], w, nv.y);
                }
            }
#pragma unroll
            for (int s = 0; s < 4; s++) {
                int q = qg + 32 * s;
                int kq = q >> 2;
                int off = ((q & 3) << 6) + n0;
                int sw = (kq & 7) << 2;
                *(ulonglong2*)(sRES + (kq << 8) + (off ^ sw)) =
                    make_ulonglong2(c[s][0], c[s][1]);
            }
        }
        __syncthreads();  // RES done; sWB4 (Wmsg) free to become ww
        stage1_ww(sA, AMg, sWB4, h, 0, tid);
        __syncthreads();

        for (int i0 = 0; i0 < 64; i0 += 16) {
            // stage2: 4-way split-K x 2 ii-halves across 8 warps, 4k x 2ii tiles
            if (tid < 256) {
                int warp = tid >> 5;
                int g = warp & 3;        // j2 quarter
                int half = warp >> 2;    // ii half
                int r = tid & 31;
                int kp = r >> 2;         // 0..7
                int iip = r & 3;         // 0..3
                int jbase = g << 6;
                int ksw = kp << 2;
                int iiA = half * 8 + iip;
                int iiB = iiA + 4;
                const float* wA = sWB4 + (iiA << 8);
                const float* wB = sWB4 + (iiB << 8);
                int swA = iiA << 2, swB = iiB << 2;
                u64 acc[4][2];
#pragma unroll
                for (int c = 0; c < 4; c++) { acc[c][0] = 0ull; acc[c][1] = 0ull; }
#pragma unroll 4
                for (int jj = 0; jj < 64; jj += 4) {
                    int j2 = jbase + jj;
                    int jx = j2 ^ ksw;
                    ulonglong2 rv[4];
#pragma unroll
                    for (int c = 0; c < 4; c++)
                        rv[c] = *(const ulonglong2*)(sRES + ((kp + 8 * c) << 8) + jx);
                    ulonglong2 wvA = *(const ulonglong2*)(wA + (j2 ^ swA));
                    ulonglong2 wvB = *(const ulonglong2*)(wB + (j2 ^ swB));
#pragma unroll
                    for (int c = 0; c < 4; c++) {
                        fma2(acc[c][0], rv[c].x, wvA.x);
                        fma2(acc[c][0], rv[c].y, wvA.y);
                        fma2(acc[c][1], rv[c].x, wvB.x);
                        fma2(acc[c][1], rv[c].y, wvB.y);
                    }
                }
                int gb = g << 9;
#pragma unroll
                for (int c = 0; c < 4; c++) {
                    int k = kp + 8 * c;
                    sPart[gb + (k << 4) + iiA] = hsum2(acc[c][0]);
                    sPart[gb + (k << 4) + iiB] = hsum2(acc[c][1]);
                }
            }
            __syncthreads();
            // stage3: reduce + gelu -> Cpad ; fused with stage1(next) or Wmsg(next head)
            {
                float v = sPart[tid] + sPart[512 + tid] + sPart[1024 + tid] + sPart[1536 + tid];
                int k = tid >> 4, ii = tid & 15;
                sCpad[(h * 32 + k) * 65 + i0 + ii] = gelu_exact(v);
            }
            if (i0 < 48) {
                stage1_ww(sA, AMg, sWB4, h, i0 + 16, tid);
            } else if (h < 3) {
                load_wmsg(sWB4, Wup, Wdn, Wlf, Wrt, tid);
            }
            __syncthreads();
        }
    }

    // ---- P5: back-projection + residual (Cpad already stride-65) ----
    float* sNIM2 = S + 16512;
    nim_calc8(sCpad, sWW, sNIM2, tid);
    __syncthreads();
    float* sPB = S;
    proj1(WBg, bBg, sNIM2, sPB, tid);
    __syncthreads();

    for (int t = tid; t < 512; t += NT) {
        int dg = t >> 4, n0 = (t & 15) << 2;
        u64 a0[2], a1[2], a2[2], a3[2];
        a0[0] = a0[1] = a1[0] = a1[1] = a2[0] = a2[1] = a3[0] = a3[1] = 0ull;
        const float* p0 = sPB + dg * PSTR;
        const float* p1 = sPB + (dg + 32) * PSTR;
        const float* p2 = sPB + (dg + 64) * PSTR;
        const float* p3 = sPB + (dg + 96) * PSTR;
        for (int j = 0; j < 75; j++) {
            int po = sPO[j];
            u64 s0 = bc2(p0[po]);
            u64 s1 = bc2(p1[po]);
            u64 s2 = bc2(p2[po]);
            u64 s3 = bc2(p3[po]);
            ulonglong2 bm = *(const ulonglong2*)(sMask + j * 64 + n0);
            fma2(a0[0], s0, bm.x); fma2(a0[1], s0, bm.y);
            fma2(a1[0], s1, bm.x); fma2(a1[1], s1, bm.y);
            fma2(a2[0], s2, bm.x); fma2(a2[1], s2, bm.y);
            fma2(a3[0], s3, bm.x); fma2(a3[1], s3, bm.y);
        }
#pragma unroll
        for (int i = 0; i < 4; i++) {
            const u64* acc = (i == 0) ? a0 : (i == 1) ? a1 : (i == 2) ? a2 : a3;
            int d = dg + 32 * i;
            int gi = d * BS + b * 64 + n0;
            ulonglong2 rr = *(const ulonglong2*)(node + gi);
            *(ulonglong2*)(outp + gi) =
                make_ulonglong2(add2(acc[0], rr.x), add2(acc[1], rr.y));
        }
    }
}

extern "C" void kernel_launch(void* const* d_in, const int* in_sizes, int n_in,
                              void* d_out, int out_size) {
    const float* node = (const float*)d_in[0];
    const float* WWg = (const float*)d_in[1];
    const float* maskg = (const float*)d_in[2];
    const float* Rg = (const float*)d_in[3];
    const float* AMg = (const float*)d_in[4];
    const float* WKg = (const float*)d_in[5];
    const float* bKg = (const float*)d_in[6];
    const float* WQg = (const float*)d_in[7];
    const float* bQg = (const float*)d_in[8];
    const float* WMg = (const float*)d_in[9];
    const float* bMg = (const float*)d_in[10];
    const float* WBg = (const float*)d_in[11];
    const float* bBg = (const float*)d_in[12];
    const float* Wup = (const float*)d_in[13];
    const float* Wdn = (const float*)d_in[14];
    const float* Wlf = (const float*)d_in[15];
    const float* Wrt = (const float*)d_in[16];
    float* outp = (float*)d_out;

    int nb = in_sizes[0] / (D * NV);
    size_t smem = SMEM_FLOATS * sizeof(float);
    cudaFuncSetAttribute(hgt_kernel, cudaFuncAttributeMaxDynamicSharedMemorySize, (int)smem);
    hgt_kernel<<<nb, NT, smem>>>(node, WWg, maskg, Rg, AMg, WKg, bKg, WQg, bQg,
                                 WMg, bMg, WBg, bBg, Wup, Wdn, Wlf, Wrt, outp, nb);
}